// round 9
// baseline (speedup 1.0000x reference)
#include <cuda_runtime.h>
#include <cuda_bf16.h>
#include <mma.h>
#include <cstdint>

using namespace nvcuda;

#define T_   4
#define B_   32
#define C_   384
#define N_   256
#define H_   8
#define D_   48
#define TB_  (T_ * B_)
#define TBH_ (TB_ * H_)
#define BCN_ (B_ * C_ * N_)      // 3,145,728
#define TOT_ (T_ * BCN_)         // 12,582,912
#define M3_  (3 * C_)            // 1152
#define BON_ (B_ * M3_ * N_)     // 9,437,184

// ---------------- scratch (device globals) ----------------------------------------
__device__ __nv_bfloat16 g_s1[TOT_];           // spikes after lif1   [tb][c][n] bf16
__device__ signed char   g_sq[TOT_];           // q spikes s8         [tb][c][n]
__device__ signed char   g_sk[TOT_];
__device__ signed char   g_sv[TOT_];
__device__ __nv_bfloat16 g_s2[TOT_];           // attn-lif spikes bf16
__device__ float         g_y3[3 * TOT_];       // fused qkv GEMM out  [tb][1152][n]
__device__ float         g_ya[TOT_];           // attention out fp32  [tb][c][n]
__device__ __nv_bfloat16 g_whi[4 * C_ * C_];   // hi bf16 of BN-scaled weights
__device__ __nv_bfloat16 g_wlo[4 * C_ * C_];   // lo residual
__device__ float         g_bns[4 * C_];        // folded BN scale
__device__ float         g_bnb[4 * C_];        // folded BN shift

// ---------------- prep ------------------------------------------------------------
__global__ void bnfold_kernel(const float* qg, const float* qb, const float* qm, const float* qv,
                              const float* kg, const float* kb, const float* km, const float* kv,
                              const float* vg, const float* vb, const float* vm, const float* vv,
                              const float* pg, const float* pb, const float* pm, const float* pv,
                              const float* pbias)
{
    int i = blockIdx.x * 256 + threadIdx.x;
    if (i >= 4 * C_) return;
    int s = i / C_, c = i - s * C_;
    const float *G, *Bt, *M, *V;
    if      (s == 0) { G = qg; Bt = qb; M = qm; V = qv; }
    else if (s == 1) { G = kg; Bt = kb; M = km; V = kv; }
    else if (s == 2) { G = vg; Bt = vb; M = vm; V = vv; }
    else             { G = pg; Bt = pb; M = pm; V = pv; }
    float inv = G[c] / sqrtf(V[c] + 1e-5f);
    float add = Bt[c] - M[c] * inv;
    if (s == 3) add += pbias[c] * inv;
    g_bns[i] = inv;
    g_bnb[i] = add;
}

// weight split with BN scale folded: W' = inv[o] * W; W' = hi + lo
__global__ void wconv_kernel(const float* __restrict__ w0, const float* __restrict__ w1,
                             const float* __restrict__ w2, const float* __restrict__ w3)
{
    int i = blockIdx.x * 256 + threadIdx.x;
    if (i >= 4 * C_ * C_) return;
    int s = i / (C_ * C_);
    int j = i - s * (C_ * C_);
    int o = j / C_;
    const float* w = (s == 0) ? w0 : (s == 1) ? w1 : (s == 2) ? w2 : w3;
    float val = w[j] * g_bns[s * C_ + o];
    __nv_bfloat16 hi = __float2bfloat16(val);
    g_whi[i] = hi;
    g_wlo[i] = __float2bfloat16(val - __bfloat162float(hi));
}

// ---------------- LIF -------------------------------------------------------------
__global__ void lif_kernel(const float* __restrict__ xin, __nv_bfloat16* __restrict__ sout)
{
    int i = blockIdx.x * 256 + threadIdx.x;
    if (i >= BCN_) return;
    float v = 0.f;
#pragma unroll
    for (int t = 0; t < T_; t++) {
        float xv = xin[(size_t)t * BCN_ + i];
        float h = v + (xv - v) * 0.5f;
        bool sp = (h >= 1.0f);
        sout[(size_t)t * BCN_ + i] = __float2bfloat16(sp ? 1.f : 0.f);
        v = sp ? 0.f : h;
    }
}

// LIF over fused qkv output -> int8 spikes for the IMMA attention
__global__ void lif3_kernel(const float* __restrict__ y,
                            signed char* __restrict__ oq,
                            signed char* __restrict__ ok,
                            signed char* __restrict__ ov)
{
    int i = blockIdx.x * 256 + threadIdx.x;
    if (i >= BON_) return;
    int n = i & (N_ - 1);
    int o = (i >> 8) % M3_;
    int b = i / (M3_ * N_);
    int s = o / C_;
    int oc = o - s * C_;
    signed char* outp = (s == 0) ? oq : (s == 1) ? ok : ov;
    size_t ibase = ((size_t)b * M3_ + o) * N_ + n;
    size_t obase = ((size_t)b * C_ + oc) * N_ + n;
    float v = 0.f;
#pragma unroll
    for (int t = 0; t < T_; t++) {
        float xv = y[(size_t)t * BON_ + ibase];
        float h = v + (xv - v) * 0.5f;
        bool sp = (h >= 1.0f);
        outp[(size_t)t * BCN_ + obase] = sp ? 1 : 0;
        v = sp ? 0.f : h;
    }
}

// ---------------- cp.async helpers ------------------------------------------------
__device__ __forceinline__ void cpa16(void* s, const void* g)
{
    unsigned int sa = (unsigned int)__cvta_generic_to_shared(s);
    asm volatile("cp.async.cg.shared.global [%0], [%1], 16;\n" :: "r"(sa), "l"(g));
}
__device__ __forceinline__ void cpa_commit() { asm volatile("cp.async.commit_group;\n"); }
template <int NN>
__device__ __forceinline__ void cpa_wait() { asm volatile("cp.async.wait_group %0;\n" :: "n"(NN)); }

// ---------------- batched GEMM + folded BN (identical to R8) ----------------------
#define GBM 128
#define GBN 256
#define GBK 64
#define LDA 72
#define LDB 264
#define LDC 260
#define NT_ 6
#define A_ST (GBM * LDA)
#define AST (2 * A_ST)
#define BST (GBK * LDB)
#define STG_ (AST + BST)
#define GSM (3 * STG_ * 2)                // 211968 B

__global__ __launch_bounds__(256, 1)
void gemm_bn_kernel(const __nv_bfloat16* __restrict__ Ahi,
                    const __nv_bfloat16* __restrict__ Alo,
                    const __nv_bfloat16* __restrict__ Bmat,
                    int ldo, int bnoff, float* __restrict__ out)
{
    extern __shared__ char smem[];
    __nv_bfloat16* Sg = (__nv_bfloat16*)smem;
    float*         Cs = (float*)smem;

    int o0 = blockIdx.x * GBM;
    int tb = blockIdx.z;
    const __nv_bfloat16* Bp = Bmat + (size_t)tb * C_ * N_;
    int tid = threadIdx.x;
    int wid = tid >> 5;
    int wm = wid & 1;
    int wn = wid >> 1;

    wmma::fragment<wmma::accumulator, 16, 16, 16, float> acc[4][4];
#pragma unroll
    for (int i = 0; i < 4; i++)
#pragma unroll
        for (int j = 0; j < 4; j++) wmma::fill_fragment(acc[i][j], 0.f);

    auto fill = [&](int kt, int st) {
        __nv_bfloat16* Ah = Sg + st * STG_;
        __nv_bfloat16* Al = Ah + A_ST;
        __nv_bfloat16* Bd = Ah + AST;
        int ka = kt * GBK;
#pragma unroll
        for (int u = 0; u < 4; u++) {
            int idx = tid + u * 256;
            int r = idx >> 3, c8 = (idx & 7) << 3;
            size_t go = (size_t)(o0 + r) * C_ + ka + c8;
            cpa16(Ah + r * LDA + c8, Ahi + go);
            cpa16(Al + r * LDA + c8, Alo + go);
        }
#pragma unroll
        for (int u = 0; u < 8; u++) {
            int idx = tid + u * 256;
            int r = idx >> 5, c8 = (idx & 31) << 3;
            cpa16(Bd + r * LDB + c8, Bp + (size_t)(ka + r) * N_ + c8);
        }
        cpa_commit();
    };

    fill(0, 0);
    fill(1, 1);
    for (int kt = 0; kt < NT_; kt++) {
        if (kt + 1 < NT_) cpa_wait<1>(); else cpa_wait<0>();
        __syncthreads();
        int st = kt % 3;
        const __nv_bfloat16* Ah = Sg + st * STG_;
        const __nv_bfloat16* Al = Ah + A_ST;
        const __nv_bfloat16* Bb = Ah + AST;
#pragma unroll
        for (int ks = 0; ks < 4; ks++) {
            wmma::fragment<wmma::matrix_b, 16, 16, 16, __nv_bfloat16, wmma::row_major> bfr[4];
#pragma unroll
            for (int j = 0; j < 4; j++)
                wmma::load_matrix_sync(bfr[j], Bb + (ks * 16) * LDB + wn * 64 + j * 16, LDB);
            wmma::fragment<wmma::matrix_a, 16, 16, 16, __nv_bfloat16, wmma::row_major> af[4];
#pragma unroll
            for (int i = 0; i < 4; i++)
                wmma::load_matrix_sync(af[i], Ah + (wm * 64 + i * 16) * LDA + ks * 16, LDA);
#pragma unroll
            for (int i = 0; i < 4; i++)
#pragma unroll
                for (int j = 0; j < 4; j++)
                    wmma::mma_sync(acc[i][j], af[i], bfr[j], acc[i][j]);
#pragma unroll
            for (int i = 0; i < 4; i++)
                wmma::load_matrix_sync(af[i], Al + (wm * 64 + i * 16) * LDA + ks * 16, LDA);
#pragma unroll
            for (int i = 0; i < 4; i++)
#pragma unroll
                for (int j = 0; j < 4; j++)
                    wmma::mma_sync(acc[i][j], af[i], bfr[j], acc[i][j]);
        }
        if (kt + 2 < NT_) fill(kt + 2, (kt + 2) % 3);
    }
    __syncthreads();

#pragma unroll
    for (int i = 0; i < 4; i++)
#pragma unroll
        for (int j = 0; j < 4; j++)
            wmma::store_matrix_sync(Cs + (wm * 64 + i * 16) * LDC + wn * 64 + j * 16,
                                    acc[i][j], LDC, wmma::mem_row_major);
    __syncthreads();

#pragma unroll
    for (int u = 0; u < 32; u++) {
        int e = tid + u * 256;
        int r = e >> 6;
        int c4 = (e & 63) << 2;
        int o = o0 + r;
        float add = g_bnb[bnoff + o];
        float4 val = *(float4*)(Cs + r * LDC + c4);
        val.x += add; val.y += add; val.z += add; val.w += add;
        *(float4*)(out + ((size_t)tb * ldo + o) * N_ + c4) = val;
    }
}

// ---------------- int8 IMMA attention ---------------------------------------------
// Per (t,b,h): S = Qt K (integers <=48, exact in s8/s32), O = V St * 0.125.
// Layout [d][n], d padded to 64. All tensor math on the integer pipe.
#define LDQ8 272    // 256 + 16 (s8, ldm mult of 16)
#define LDS8 80     // 64 + 16
#define LDO8 68     // int, ldm mult of 4
#define AQ8  0
#define AK8  (64 * LDQ8)
#define AV8  (2 * 64 * LDQ8)
#define AST8 (3 * 64 * LDQ8)                       // 52224
#define ASC8 (AST8 + 256 * LDS8)                   // 72704
#define AOS8 (ASC8 + 8 * 256 * 4)                  // 80896
#define ASM8 (AOS8 + 64 * LDO8 * 4)                // 98304

__global__ __launch_bounds__(256)
void attn_kernel(const signed char* __restrict__ q, const signed char* __restrict__ k,
                 const signed char* __restrict__ v, float* __restrict__ out)
{
    extern __shared__ char smraw[];
    signed char* Qs = (signed char*)(smraw + AQ8);     // [64][LDQ8]
    signed char* Ks = (signed char*)(smraw + AK8);
    signed char* Vs = (signed char*)(smraw + AV8);
    signed char* STb = (signed char*)(smraw + AST8);   // S^T [256][LDS8]
    int* scratch = (int*)(smraw + ASC8);               // 8 warps x 256 int
    int* Osm = (int*)(smraw + AOS8);                   // [64][LDO8]

    int blk = blockIdx.x;
    int tb = blk >> 3, h = blk & 7;
    size_t base = ((size_t)tb * C_ + h * D_) * N_;
    int tid = threadIdx.x;
    int wid = tid >> 5;
    int lane = tid & 31;

    // load Q,K,V head slices [48][256] s8 (rows 48..63 zeroed), 16B chunks
    const signed char* srcs[3] = { q + base, k + base, v + base };
    signed char* dsts[3] = { Qs, Ks, Vs };
#pragma unroll
    for (int mtx = 0; mtx < 3; mtx++) {
#pragma unroll
        for (int u = 0; u < 4; u++) {
            int idx = tid + u * 256;
            int r = idx >> 4, col = (idx & 15) << 4;
            uint4 val = (r < 48) ? *(const uint4*)(srcs[mtx] + (size_t)r * N_ + col)
                                 : make_uint4(0, 0, 0, 0);
            *(uint4*)(dsts[mtx] + r * LDQ8 + col) = val;
        }
    }
    __syncthreads();

    int wr = wid & 1;       // stage1: S rows (n') wr*32.., cols (m) wc*64..
    int wc = wid >> 1;

#pragma unroll 1
    for (int nt = 0; nt < 4; nt++) {
        int n0 = nt * 64;

        // ---- stage 1: S[n0+0..63][0..255] = Q^T K (s32) ----
        wmma::fragment<wmma::accumulator, 16, 16, 16, int> sacc[2][4];
#pragma unroll
        for (int i = 0; i < 2; i++)
#pragma unroll
            for (int j = 0; j < 4; j++) wmma::fill_fragment(sacc[i][j], 0);
#pragma unroll
        for (int dk = 0; dk < 64; dk += 16) {
            wmma::fragment<wmma::matrix_a, 16, 16, 16, signed char, wmma::col_major> af[2];
            wmma::fragment<wmma::matrix_b, 16, 16, 16, signed char, wmma::row_major> bfr[4];
#pragma unroll
            for (int i = 0; i < 2; i++)
                wmma::load_matrix_sync(af[i], Qs + dk * LDQ8 + n0 + wr * 32 + i * 16, LDQ8);
#pragma unroll
            for (int j = 0; j < 4; j++)
                wmma::load_matrix_sync(bfr[j], Ks + dk * LDQ8 + wc * 64 + j * 16, LDQ8);
#pragma unroll
            for (int i = 0; i < 2; i++)
#pragma unroll
                for (int j = 0; j < 4; j++)
                    wmma::mma_sync(sacc[i][j], af[i], bfr[j], sacc[i][j]);
        }
        // S (s32, <=48) -> s8 S^T in smem
        int* scr = scratch + wid * 256;
#pragma unroll
        for (int i = 0; i < 2; i++)
#pragma unroll
            for (int j = 0; j < 4; j++) {
                wmma::store_matrix_sync(scr, sacc[i][j], 16, wmma::mem_col_major);
                __syncwarp();
#pragma unroll
                for (int e = 0; e < 8; e++) {
                    int idx = lane + e * 32;
                    int ni = idx & 15, mj = idx >> 4;
                    STb[(wc * 64 + j * 16 + mj) * LDS8 + wr * 32 + i * 16 + ni] =
                        (signed char)scr[idx];
                }
                __syncwarp();
            }
        __syncthreads();

        // ---- stage 2: O[0..63][n0..n0+63] = V S^T (s32) ----
        int dr = wid & 1;   // d rows dr*32..
        int nc = wid >> 1;  // n' cols nc*16..
        wmma::fragment<wmma::accumulator, 16, 16, 16, int> oacc[2];
#pragma unroll
        for (int i = 0; i < 2; i++) wmma::fill_fragment(oacc[i], 0);
#pragma unroll
        for (int m = 0; m < 256; m += 16) {
            wmma::fragment<wmma::matrix_a, 16, 16, 16, signed char, wmma::row_major> av[2];
            wmma::fragment<wmma::matrix_b, 16, 16, 16, signed char, wmma::row_major> bs;
#pragma unroll
            for (int i = 0; i < 2; i++)
                wmma::load_matrix_sync(av[i], Vs + (dr * 32 + i * 16) * LDQ8 + m, LDQ8);
            wmma::load_matrix_sync(bs, STb + m * LDS8 + nc * 16, LDS8);
#pragma unroll
            for (int i = 0; i < 2; i++)
                wmma::mma_sync(oacc[i], av[i], bs, oacc[i]);
        }
#pragma unroll
        for (int i = 0; i < 2; i++)
            wmma::store_matrix_sync(Osm + (dr * 32 + i * 16) * LDO8 + nc * 16,
                                    oacc[i], LDO8, wmma::mem_row_major);
        __syncthreads();

        // write d<48 rows as fp32 * 0.125
#pragma unroll
        for (int u = 0; u < 3; u++) {
            int e = tid + u * 256;
            int d = e >> 4, c4 = (e & 15) << 2;
            int4 iv = *(int4*)(Osm + d * LDO8 + c4);
            float4 val;
            val.x = iv.x * 0.125f;
            val.y = iv.y * 0.125f;
            val.z = iv.z * 0.125f;
            val.w = iv.w * 0.125f;
            *(float4*)(out + base + (size_t)d * N_ + n0 + c4) = val;
        }
        __syncthreads();
    }
}

// ---------------- launch ----------------------------------------------------------
extern "C" void kernel_launch(void* const* d_in, const int* in_sizes, int n_in,
                              void* d_out, int out_size)
{
    const float* x   = (const float*)d_in[0];
    const float* qw  = (const float*)d_in[2];
    const float* qg  = (const float*)d_in[3];
    const float* qb  = (const float*)d_in[4];
    const float* qm  = (const float*)d_in[5];
    const float* qv  = (const float*)d_in[6];
    const float* kw  = (const float*)d_in[7];
    const float* kg  = (const float*)d_in[8];
    const float* kb  = (const float*)d_in[9];
    const float* km  = (const float*)d_in[10];
    const float* kv  = (const float*)d_in[11];
    const float* vw  = (const float*)d_in[12];
    const float* vg  = (const float*)d_in[13];
    const float* vb  = (const float*)d_in[14];
    const float* vm  = (const float*)d_in[15];
    const float* vv  = (const float*)d_in[16];
    const float* pw  = (const float*)d_in[17];
    const float* pbias = (const float*)d_in[18];
    const float* pg  = (const float*)d_in[19];
    const float* pb  = (const float*)d_in[20];
    const float* pm  = (const float*)d_in[21];
    const float* pv  = (const float*)d_in[22];

    void *ps1, *psq, *psk, *psv, *ps2, *py3, *pya, *phi, *plo;
    cudaGetSymbolAddress(&ps1, g_s1);
    cudaGetSymbolAddress(&psq, g_sq);
    cudaGetSymbolAddress(&psk, g_sk);
    cudaGetSymbolAddress(&psv, g_sv);
    cudaGetSymbolAddress(&ps2, g_s2);
    cudaGetSymbolAddress(&py3, g_y3);
    cudaGetSymbolAddress(&pya, g_ya);
    cudaGetSymbolAddress(&phi, g_whi);
    cudaGetSymbolAddress(&plo, g_wlo);
    __nv_bfloat16* s1  = (__nv_bfloat16*)ps1;
    signed char*   sq  = (signed char*)psq;
    signed char*   sk  = (signed char*)psk;
    signed char*   sv  = (signed char*)psv;
    __nv_bfloat16* s2  = (__nv_bfloat16*)ps2;
    float*         y3  = (float*)py3;
    float*         ya  = (float*)pya;
    __nv_bfloat16* whi = (__nv_bfloat16*)phi;
    __nv_bfloat16* wlo = (__nv_bfloat16*)plo;

    cudaFuncSetAttribute(gemm_bn_kernel, cudaFuncAttributeMaxDynamicSharedMemorySize, GSM);
    cudaFuncSetAttribute(attn_kernel, cudaFuncAttributeMaxDynamicSharedMemorySize, ASM8);

    // prep: BN fold first (wconv consumes g_bns)
    bnfold_kernel<<<6, 256>>>(qg, qb, qm, qv, kg, kb, km, kv,
                              vg, vb, vm, vv, pg, pb, pm, pv, pbias);
    wconv_kernel<<<(4 * C_ * C_ + 255) / 256, 256>>>(qw, kw, vw, pw);
    // proj_lif on input
    lif_kernel<<<BCN_ / 256, 256>>>(x, s1);
    // fused q,k,v GEMM + BN: 9 o-tiles x 128 tb
    gemm_bn_kernel<<<dim3(M3_ / GBM, 1, TB_), 256, GSM>>>(
        whi, wlo, s1, M3_, 0, y3);
    // LIF over the three branches -> s8 spikes
    lif3_kernel<<<BON_ / 256, 256>>>(y3, sq, sk, sv);
    // int8 IMMA attention -> fp32
    attn_kernel<<<TBH_, 256, ASM8>>>(sq, sk, sv, ya);
    // attn_lif
    lif_kernel<<<BCN_ / 256, 256>>>(ya, s2);
    // proj GEMM + bias + BN -> final output
    gemm_bn_kernel<<<dim3(C_ / GBM, 1, TB_), 256, GSM>>>(
        whi + 3 * C_ * C_, wlo + 3 * C_ * C_, s2, C_, 3 * C_, (float*)d_out);
}

// round 10
// speedup vs baseline: 1.2653x; 1.2653x over previous
#include <cuda_runtime.h>
#include <cuda_bf16.h>
#include <mma.h>
#include <cstdint>

using namespace nvcuda;

#define T_   4
#define B_   32
#define C_   384
#define N_   256
#define H_   8
#define D_   48
#define TB_  (T_ * B_)
#define TBH_ (TB_ * H_)
#define BCN_ (B_ * C_ * N_)      // 3,145,728
#define TOT_ (T_ * BCN_)         // 12,582,912
#define M3_  (3 * C_)            // 1152
#define BON_ (B_ * M3_ * N_)     // 9,437,184

// ---------------- scratch (device globals) ----------------------------------------
__device__ __nv_bfloat16 g_s1[TOT_];           // spikes after lif1   [tb][c][n]
__device__ __nv_bfloat16 g_sq[TOT_];           // q spikes            [tb][c][n]
__device__ __nv_bfloat16 g_sk[TOT_];
__device__ __nv_bfloat16 g_sv[TOT_];
__device__ __nv_bfloat16 g_s2[TOT_];           // attn-lif spikes
__device__ float         g_y3[3 * TOT_];       // fused qkv GEMM out  [tb][1152][n]
__device__ float         g_ya[TOT_];           // attention out fp32  [tb][c][n]
__device__ __nv_bfloat16 g_whi[4 * C_ * C_];   // hi bf16 of BN-scaled weights
__device__ __nv_bfloat16 g_wlo[4 * C_ * C_];   // lo residual
__device__ float         g_bns[4 * C_];        // folded BN scale
__device__ float         g_bnb[4 * C_];        // folded BN shift

// ---------------- prep ------------------------------------------------------------
__global__ void bnfold_kernel(const float* qg, const float* qb, const float* qm, const float* qv,
                              const float* kg, const float* kb, const float* km, const float* kv,
                              const float* vg, const float* vb, const float* vm, const float* vv,
                              const float* pg, const float* pb, const float* pm, const float* pv,
                              const float* pbias)
{
    int i = blockIdx.x * 256 + threadIdx.x;
    if (i >= 4 * C_) return;
    int s = i / C_, c = i - s * C_;
    const float *G, *Bt, *M, *V;
    if      (s == 0) { G = qg; Bt = qb; M = qm; V = qv; }
    else if (s == 1) { G = kg; Bt = kb; M = km; V = kv; }
    else if (s == 2) { G = vg; Bt = vb; M = vm; V = vv; }
    else             { G = pg; Bt = pb; M = pm; V = pv; }
    float inv = G[c] / sqrtf(V[c] + 1e-5f);
    float add = Bt[c] - M[c] * inv;
    if (s == 3) add += pbias[c] * inv;
    g_bns[i] = inv;
    g_bnb[i] = add;
}

// weight split with BN scale folded: W' = inv[o] * W; W' = hi + lo
__global__ void wconv_kernel(const float* __restrict__ w0, const float* __restrict__ w1,
                             const float* __restrict__ w2, const float* __restrict__ w3)
{
    int i = blockIdx.x * 256 + threadIdx.x;
    if (i >= 4 * C_ * C_) return;
    int s = i / (C_ * C_);
    int j = i - s * (C_ * C_);
    int o = j / C_;
    const float* w = (s == 0) ? w0 : (s == 1) ? w1 : (s == 2) ? w2 : w3;
    float val = w[j] * g_bns[s * C_ + o];
    __nv_bfloat16 hi = __float2bfloat16(val);
    g_whi[i] = hi;
    g_wlo[i] = __float2bfloat16(val - __bfloat162float(hi));
}

// ---------------- LIF -------------------------------------------------------------
__global__ void lif_kernel(const float* __restrict__ xin, __nv_bfloat16* __restrict__ sout)
{
    int i = blockIdx.x * 256 + threadIdx.x;
    if (i >= BCN_) return;
    float v = 0.f;
#pragma unroll
    for (int t = 0; t < T_; t++) {
        float xv = xin[(size_t)t * BCN_ + i];
        float h = v + (xv - v) * 0.5f;
        bool sp = (h >= 1.0f);
        sout[(size_t)t * BCN_ + i] = __float2bfloat16(sp ? 1.f : 0.f);
        v = sp ? 0.f : h;
    }
}

__global__ void lif3_kernel(const float* __restrict__ y,
                            __nv_bfloat16* __restrict__ oq,
                            __nv_bfloat16* __restrict__ ok,
                            __nv_bfloat16* __restrict__ ov)
{
    int i = blockIdx.x * 256 + threadIdx.x;
    if (i >= BON_) return;
    int n = i & (N_ - 1);
    int o = (i >> 8) % M3_;
    int b = i / (M3_ * N_);
    int s = o / C_;
    int oc = o - s * C_;
    __nv_bfloat16* outp = (s == 0) ? oq : (s == 1) ? ok : ov;
    size_t ibase = ((size_t)b * M3_ + o) * N_ + n;
    size_t obase = ((size_t)b * C_ + oc) * N_ + n;
    float v = 0.f;
#pragma unroll
    for (int t = 0; t < T_; t++) {
        float xv = y[(size_t)t * BON_ + ibase];
        float h = v + (xv - v) * 0.5f;
        bool sp = (h >= 1.0f);
        outp[(size_t)t * BCN_ + obase] = __float2bfloat16(sp ? 1.f : 0.f);
        v = sp ? 0.f : h;
    }
}

// ---------------- cp.async helpers ------------------------------------------------
__device__ __forceinline__ void cpa16(void* s, const void* g)
{
    unsigned int sa = (unsigned int)__cvta_generic_to_shared(s);
    asm volatile("cp.async.cg.shared.global [%0], [%1], 16;\n" :: "r"(sa), "l"(g));
}
__device__ __forceinline__ void cpa_commit() { asm volatile("cp.async.commit_group;\n"); }
template <int NN>
__device__ __forceinline__ void cpa_wait() { asm volatile("cp.async.wait_group %0;\n" :: "n"(NN)); }

// ---------------- batched GEMM + folded BN (identical to R8) ----------------------
#define GBM 128
#define GBN 256
#define GBK 64
#define LDA 72
#define LDB 264
#define LDC 260
#define NT_ 6
#define A_ST (GBM * LDA)
#define AST (2 * A_ST)
#define BST (GBK * LDB)
#define STG_ (AST + BST)
#define GSM (3 * STG_ * 2)                // 211968 B

__global__ __launch_bounds__(256, 1)
void gemm_bn_kernel(const __nv_bfloat16* __restrict__ Ahi,
                    const __nv_bfloat16* __restrict__ Alo,
                    const __nv_bfloat16* __restrict__ Bmat,
                    int ldo, int bnoff, float* __restrict__ out)
{
    extern __shared__ char smem[];
    __nv_bfloat16* Sg = (__nv_bfloat16*)smem;
    float*         Cs = (float*)smem;

    int o0 = blockIdx.x * GBM;
    int tb = blockIdx.z;
    const __nv_bfloat16* Bp = Bmat + (size_t)tb * C_ * N_;
    int tid = threadIdx.x;
    int wid = tid >> 5;
    int wm = wid & 1;
    int wn = wid >> 1;

    wmma::fragment<wmma::accumulator, 16, 16, 16, float> acc[4][4];
#pragma unroll
    for (int i = 0; i < 4; i++)
#pragma unroll
        for (int j = 0; j < 4; j++) wmma::fill_fragment(acc[i][j], 0.f);

    auto fill = [&](int kt, int st) {
        __nv_bfloat16* Ah = Sg + st * STG_;
        __nv_bfloat16* Al = Ah + A_ST;
        __nv_bfloat16* Bd = Ah + AST;
        int ka = kt * GBK;
#pragma unroll
        for (int u = 0; u < 4; u++) {
            int idx = tid + u * 256;
            int r = idx >> 3, c8 = (idx & 7) << 3;
            size_t go = (size_t)(o0 + r) * C_ + ka + c8;
            cpa16(Ah + r * LDA + c8, Ahi + go);
            cpa16(Al + r * LDA + c8, Alo + go);
        }
#pragma unroll
        for (int u = 0; u < 8; u++) {
            int idx = tid + u * 256;
            int r = idx >> 5, c8 = (idx & 31) << 3;
            cpa16(Bd + r * LDB + c8, Bp + (size_t)(ka + r) * N_ + c8);
        }
        cpa_commit();
    };

    fill(0, 0);
    fill(1, 1);
    for (int kt = 0; kt < NT_; kt++) {
        if (kt + 1 < NT_) cpa_wait<1>(); else cpa_wait<0>();
        __syncthreads();
        int st = kt % 3;
        const __nv_bfloat16* Ah = Sg + st * STG_;
        const __nv_bfloat16* Al = Ah + A_ST;
        const __nv_bfloat16* Bb = Ah + AST;
#pragma unroll
        for (int ks = 0; ks < 4; ks++) {
            wmma::fragment<wmma::matrix_b, 16, 16, 16, __nv_bfloat16, wmma::row_major> bfr[4];
#pragma unroll
            for (int j = 0; j < 4; j++)
                wmma::load_matrix_sync(bfr[j], Bb + (ks * 16) * LDB + wn * 64 + j * 16, LDB);
            wmma::fragment<wmma::matrix_a, 16, 16, 16, __nv_bfloat16, wmma::row_major> af[4];
#pragma unroll
            for (int i = 0; i < 4; i++)
                wmma::load_matrix_sync(af[i], Ah + (wm * 64 + i * 16) * LDA + ks * 16, LDA);
#pragma unroll
            for (int i = 0; i < 4; i++)
#pragma unroll
                for (int j = 0; j < 4; j++)
                    wmma::mma_sync(acc[i][j], af[i], bfr[j], acc[i][j]);
#pragma unroll
            for (int i = 0; i < 4; i++)
                wmma::load_matrix_sync(af[i], Al + (wm * 64 + i * 16) * LDA + ks * 16, LDA);
#pragma unroll
            for (int i = 0; i < 4; i++)
#pragma unroll
                for (int j = 0; j < 4; j++)
                    wmma::mma_sync(acc[i][j], af[i], bfr[j], acc[i][j]);
        }
        if (kt + 2 < NT_) fill(kt + 2, (kt + 2) % 3);
    }
    __syncthreads();

#pragma unroll
    for (int i = 0; i < 4; i++)
#pragma unroll
        for (int j = 0; j < 4; j++)
            wmma::store_matrix_sync(Cs + (wm * 64 + i * 16) * LDC + wn * 64 + j * 16,
                                    acc[i][j], LDC, wmma::mem_row_major);
    __syncthreads();

#pragma unroll
    for (int u = 0; u < 32; u++) {
        int e = tid + u * 256;
        int r = e >> 6;
        int c4 = (e & 63) << 2;
        int o = o0 + r;
        float add = g_bnb[bnoff + o];
        float4 val = *(float4*)(Cs + r * LDC + c4);
        val.x += add; val.y += add; val.z += add; val.w += add;
        *(float4*)(out + ((size_t)tb * ldo + o) * N_ + c4) = val;
    }
}

// ---------------- tensor-core attention (bf16, optimized S conversion) -------------
// Per (t,b,h), per 64-wide n' stripe:
//   stage1: St[m][n'] = K^T Q   (transpose for free via operand roles)
//   convert: fp32 St tile -> bf16 (vectorized, one pass)
//   stage2: O[d][n'] = V St, scaled by 0.125
#define LDQ 264     // bf16 row of 256 + 8
#define LDSF 68     // fp32 St row: 64 + 4
#define LDS2 72     // bf16 St row: 64 + 8
#define LDO 68      // fp32 O row: 64 + 4
#define AQ_  0
#define AK_  (64 * LDQ * 2)
#define AV_  (2 * 64 * LDQ * 2)
#define ASF_ (3 * 64 * LDQ * 2)                // Sfp (and Osm alias)
#define AST2 (ASF_ + 256 * LDSF * 4)           // St bf16
#define ASM_ (AST2 + 256 * LDS2 * 2)           // 207872 B

__global__ __launch_bounds__(256)
void attn_kernel(const __nv_bfloat16* __restrict__ q, const __nv_bfloat16* __restrict__ k,
                 const __nv_bfloat16* __restrict__ v, float* __restrict__ out)
{
    extern __shared__ char smraw[];
    __nv_bfloat16* Qs = (__nv_bfloat16*)(smraw + AQ_);   // [64][LDQ] rows d, cols n
    __nv_bfloat16* Ks = (__nv_bfloat16*)(smraw + AK_);
    __nv_bfloat16* Vs = (__nv_bfloat16*)(smraw + AV_);
    float*         Sfp = (float*)(smraw + ASF_);         // [256 m][LDSF]
    float*         Osm = (float*)(smraw + ASF_);         // alias (Sfp dead in stage2)
    __nv_bfloat16* Stb = (__nv_bfloat16*)(smraw + AST2); // [256 m][LDS2]

    int blk = blockIdx.x;
    int tb = blk >> 3, h = blk & 7;
    size_t base = ((size_t)tb * C_ + h * D_) * N_;
    int tid = threadIdx.x;
    int wid = tid >> 5;

    // load Q,K,V head slices [48][256] bf16, rows 48..63 zero-padded
    const __nv_bfloat16* srcs[3] = { q + base, k + base, v + base };
    __nv_bfloat16* dsts[3] = { Qs, Ks, Vs };
#pragma unroll
    for (int mtx = 0; mtx < 3; mtx++) {
#pragma unroll
        for (int u = 0; u < 6; u++) {
            int idx = tid + u * 256;
            int r = idx >> 5, col = (idx & 31) << 3;
            *(uint4*)(dsts[mtx] + r * LDQ + col) = *(const uint4*)(srcs[mtx] + (size_t)r * N_ + col);
        }
#pragma unroll
        for (int u = 0; u < 2; u++) {
            int idx = tid + u * 256;
            int r = 48 + (idx >> 5), col = (idx & 31) << 3;
            *(uint4*)(dsts[mtx] + r * LDQ + col) = make_uint4(0, 0, 0, 0);
        }
    }
    __syncthreads();

#pragma unroll 1
    for (int nt = 0; nt < 4; nt++) {
        int n0 = nt * 64;

        // ---- stage 1: St[m 0..255][n' 0..63] = K^T Q ----
        {
            int wm2 = wid & 3;      // 4 warps over m (64 each)
            int wn2 = wid >> 2;     // 2 warps over n' (32 each)
            wmma::fragment<wmma::accumulator, 16, 16, 16, float> sacc[4][2];
#pragma unroll
            for (int i = 0; i < 4; i++)
#pragma unroll
                for (int j = 0; j < 2; j++) wmma::fill_fragment(sacc[i][j], 0.f);
#pragma unroll
            for (int dk = 0; dk < 64; dk += 16) {
                wmma::fragment<wmma::matrix_a, 16, 16, 16, __nv_bfloat16, wmma::col_major> ak[4];
                wmma::fragment<wmma::matrix_b, 16, 16, 16, __nv_bfloat16, wmma::row_major> bq[2];
#pragma unroll
                for (int i = 0; i < 4; i++)
                    wmma::load_matrix_sync(ak[i], Ks + dk * LDQ + wm2 * 64 + i * 16, LDQ);
#pragma unroll
                for (int j = 0; j < 2; j++)
                    wmma::load_matrix_sync(bq[j], Qs + dk * LDQ + n0 + wn2 * 32 + j * 16, LDQ);
#pragma unroll
                for (int i = 0; i < 4; i++)
#pragma unroll
                    for (int j = 0; j < 2; j++)
                        wmma::mma_sync(sacc[i][j], ak[i], bq[j], sacc[i][j]);
            }
#pragma unroll
            for (int i = 0; i < 4; i++)
#pragma unroll
                for (int j = 0; j < 2; j++)
                    wmma::store_matrix_sync(Sfp + (wm2 * 64 + i * 16) * LDSF + wn2 * 32 + j * 16,
                                            sacc[i][j], LDSF, wmma::mem_row_major);
        }
        __syncthreads();

        // ---- convert Sfp (fp32) -> Stb (bf16), vectorized ----
#pragma unroll
        for (int u = 0; u < 16; u++) {     // 4096 float4 groups = 16384 elems
            int idx = tid + u * 256;
            int m = idx >> 4, c4 = (idx & 15) << 2;
            float4 val = *(float4*)(Sfp + m * LDSF + c4);
            __nv_bfloat162 p0 = __floats2bfloat162_rn(val.x, val.y);
            __nv_bfloat162 p1 = __floats2bfloat162_rn(val.z, val.w);
            uint2 w;
            w.x = *(unsigned int*)&p0;
            w.y = *(unsigned int*)&p1;
            *(uint2*)(Stb + m * LDS2 + c4) = w;
        }
        __syncthreads();

        // ---- stage 2: O[d 0..63][n' 0..63] = V St ----
        {
            int dr = wid & 1;       // 2 warps over d (32 each)
            int nc = wid >> 1;      // 4 warps over n' (16 each)
            wmma::fragment<wmma::accumulator, 16, 16, 16, float> oacc[2];
#pragma unroll
            for (int i = 0; i < 2; i++) wmma::fill_fragment(oacc[i], 0.f);
#pragma unroll
            for (int m = 0; m < 256; m += 16) {
                wmma::fragment<wmma::matrix_a, 16, 16, 16, __nv_bfloat16, wmma::row_major> av[2];
                wmma::fragment<wmma::matrix_b, 16, 16, 16, __nv_bfloat16, wmma::row_major> bs;
#pragma unroll
                for (int i = 0; i < 2; i++)
                    wmma::load_matrix_sync(av[i], Vs + (dr * 32 + i * 16) * LDQ + m, LDQ);
                wmma::load_matrix_sync(bs, Stb + m * LDS2 + nc * 16, LDS2);
#pragma unroll
                for (int i = 0; i < 2; i++)
                    wmma::mma_sync(oacc[i], av[i], bs, oacc[i]);
            }
#pragma unroll
            for (int i = 0; i < 2; i++)
                wmma::store_matrix_sync(Osm + (dr * 32 + i * 16) * LDO + nc * 16,
                                        oacc[i], LDO, wmma::mem_row_major);
        }
        __syncthreads();

        // ---- write d<48 rows, scaled 0.125 ----
#pragma unroll
        for (int u = 0; u < 3; u++) {
            int e = tid + u * 256;
            int d = e >> 4, c4 = (e & 15) << 2;
            float4 val = *(float4*)(Osm + d * LDO + c4);
            val.x *= 0.125f; val.y *= 0.125f; val.z *= 0.125f; val.w *= 0.125f;
            *(float4*)(out + base + (size_t)d * N_ + n0 + c4) = val;
        }
        __syncthreads();
    }
}

// ---------------- launch ----------------------------------------------------------
extern "C" void kernel_launch(void* const* d_in, const int* in_sizes, int n_in,
                              void* d_out, int out_size)
{
    const float* x   = (const float*)d_in[0];
    const float* qw  = (const float*)d_in[2];
    const float* qg  = (const float*)d_in[3];
    const float* qb  = (const float*)d_in[4];
    const float* qm  = (const float*)d_in[5];
    const float* qv  = (const float*)d_in[6];
    const float* kw  = (const float*)d_in[7];
    const float* kg  = (const float*)d_in[8];
    const float* kb  = (const float*)d_in[9];
    const float* km  = (const float*)d_in[10];
    const float* kv  = (const float*)d_in[11];
    const float* vw  = (const float*)d_in[12];
    const float* vg  = (const float*)d_in[13];
    const float* vb  = (const float*)d_in[14];
    const float* vm  = (const float*)d_in[15];
    const float* vv  = (const float*)d_in[16];
    const float* pw  = (const float*)d_in[17];
    const float* pbias = (const float*)d_in[18];
    const float* pg  = (const float*)d_in[19];
    const float* pb  = (const float*)d_in[20];
    const float* pm  = (const float*)d_in[21];
    const float* pv  = (const float*)d_in[22];

    void *ps1, *psq, *psk, *psv, *ps2, *py3, *pya, *phi, *plo;
    cudaGetSymbolAddress(&ps1, g_s1);
    cudaGetSymbolAddress(&psq, g_sq);
    cudaGetSymbolAddress(&psk, g_sk);
    cudaGetSymbolAddress(&psv, g_sv);
    cudaGetSymbolAddress(&ps2, g_s2);
    cudaGetSymbolAddress(&py3, g_y3);
    cudaGetSymbolAddress(&pya, g_ya);
    cudaGetSymbolAddress(&phi, g_whi);
    cudaGetSymbolAddress(&plo, g_wlo);
    __nv_bfloat16* s1  = (__nv_bfloat16*)ps1;
    __nv_bfloat16* sq  = (__nv_bfloat16*)psq;
    __nv_bfloat16* sk  = (__nv_bfloat16*)psk;
    __nv_bfloat16* sv  = (__nv_bfloat16*)psv;
    __nv_bfloat16* s2  = (__nv_bfloat16*)ps2;
    float*         y3  = (float*)py3;
    float*         ya  = (float*)pya;
    __nv_bfloat16* whi = (__nv_bfloat16*)phi;
    __nv_bfloat16* wlo = (__nv_bfloat16*)plo;

    cudaFuncSetAttribute(gemm_bn_kernel, cudaFuncAttributeMaxDynamicSharedMemorySize, GSM);
    cudaFuncSetAttribute(attn_kernel, cudaFuncAttributeMaxDynamicSharedMemorySize, ASM_);

    // prep: BN fold first (wconv consumes g_bns)
    bnfold_kernel<<<6, 256>>>(qg, qb, qm, qv, kg, kb, km, kv,
                              vg, vb, vm, vv, pg, pb, pm, pv, pbias);
    wconv_kernel<<<(4 * C_ * C_ + 255) / 256, 256>>>(qw, kw, vw, pw);
    // proj_lif on input
    lif_kernel<<<BCN_ / 256, 256>>>(x, s1);
    // fused q,k,v GEMM + BN: 9 o-tiles x 128 tb
    gemm_bn_kernel<<<dim3(M3_ / GBM, 1, TB_), 256, GSM>>>(
        whi, wlo, s1, M3_, 0, y3);
    // LIF over the three branches
    lif3_kernel<<<BON_ / 256, 256>>>(y3, sq, sk, sv);
    // bf16 tensor attention -> fp32
    attn_kernel<<<TBH_, 256, ASM_>>>(sq, sk, sv, ya);
    // attn_lif
    lif_kernel<<<BCN_ / 256, 256>>>(ya, s2);
    // proj GEMM + bias + BN -> final output
    gemm_bn_kernel<<<dim3(C_ / GBM, 1, TB_), 256, GSM>>>(
        whi + 3 * C_ * C_, wlo + 3 * C_ * C_, s2, C_, 3 * C_, (float*)d_out);
}

// round 11
// speedup vs baseline: 1.2891x; 1.0188x over previous
#include <cuda_runtime.h>
#include <cuda_bf16.h>
#include <mma.h>
#include <cstdint>

using namespace nvcuda;

#define T_   4
#define B_   32
#define C_   384
#define N_   256
#define H_   8
#define D_   48
#define TB_  (T_ * B_)
#define TBH_ (TB_ * H_)
#define BCN_ (B_ * C_ * N_)      // 3,145,728
#define TOT_ (T_ * BCN_)         // 12,582,912
#define M3_  (3 * C_)            // 1152

// ---------------- scratch (device globals) ----------------------------------------
__device__ __nv_bfloat16 g_s1[TOT_];           // spikes after lif1   [tb][c][n]
__device__ __nv_bfloat16 g_sq[TOT_];           // q spikes            [tb][c][n]
__device__ __nv_bfloat16 g_sk[TOT_];
__device__ __nv_bfloat16 g_sv[TOT_];
__device__ __nv_bfloat16 g_s2[TOT_];           // attn-lif spikes
__device__ float         g_ya[TOT_];           // attention out fp32  [tb][c][n]
__device__ __nv_bfloat16 g_whi[4 * C_ * C_];   // hi bf16 of BN-scaled weights
__device__ __nv_bfloat16 g_wlo[4 * C_ * C_];   // lo residual
__device__ float         g_bns[4 * C_];        // folded BN scale
__device__ float         g_bnb[4 * C_];        // folded BN shift

// ---------------- prep ------------------------------------------------------------
__global__ void bnfold_kernel(const float* qg, const float* qb, const float* qm, const float* qv,
                              const float* kg, const float* kb, const float* km, const float* kv,
                              const float* vg, const float* vb, const float* vm, const float* vv,
                              const float* pg, const float* pb, const float* pm, const float* pv,
                              const float* pbias)
{
    int i = blockIdx.x * 256 + threadIdx.x;
    if (i >= 4 * C_) return;
    int s = i / C_, c = i - s * C_;
    const float *G, *Bt, *M, *V;
    if      (s == 0) { G = qg; Bt = qb; M = qm; V = qv; }
    else if (s == 1) { G = kg; Bt = kb; M = km; V = kv; }
    else if (s == 2) { G = vg; Bt = vb; M = vm; V = vv; }
    else             { G = pg; Bt = pb; M = pm; V = pv; }
    float inv = G[c] / sqrtf(V[c] + 1e-5f);
    float add = Bt[c] - M[c] * inv;
    if (s == 3) add += pbias[c] * inv;
    g_bns[i] = inv;
    g_bnb[i] = add;
}

// weight split with BN scale folded: W' = inv[o] * W; W' = hi + lo
__global__ void wconv_kernel(const float* __restrict__ w0, const float* __restrict__ w1,
                             const float* __restrict__ w2, const float* __restrict__ w3)
{
    int i = blockIdx.x * 256 + threadIdx.x;
    if (i >= 4 * C_ * C_) return;
    int s = i / (C_ * C_);
    int j = i - s * (C_ * C_);
    int o = j / C_;
    const float* w = (s == 0) ? w0 : (s == 1) ? w1 : (s == 2) ? w2 : w3;
    float val = w[j] * g_bns[s * C_ + o];
    __nv_bfloat16 hi = __float2bfloat16(val);
    g_whi[i] = hi;
    g_wlo[i] = __float2bfloat16(val - __bfloat162float(hi));
}

// ---------------- LIF -------------------------------------------------------------
__global__ void lif_kernel(const float* __restrict__ xin, __nv_bfloat16* __restrict__ sout)
{
    int i = blockIdx.x * 256 + threadIdx.x;
    if (i >= BCN_) return;
    float v = 0.f;
#pragma unroll
    for (int t = 0; t < T_; t++) {
        float xv = xin[(size_t)t * BCN_ + i];
        float h = v + (xv - v) * 0.5f;
        bool sp = (h >= 1.0f);
        sout[(size_t)t * BCN_ + i] = __float2bfloat16(sp ? 1.f : 0.f);
        v = sp ? 0.f : h;
    }
}

// ---------------- cp.async helpers ------------------------------------------------
__device__ __forceinline__ void cpa16(void* s, const void* g)
{
    unsigned int sa = (unsigned int)__cvta_generic_to_shared(s);
    asm volatile("cp.async.cg.shared.global [%0], [%1], 16;\n" :: "r"(sa), "l"(g));
}
__device__ __forceinline__ void cpa_commit() { asm volatile("cp.async.commit_group;\n"); }
template <int NN>
__device__ __forceinline__ void cpa_wait() { asm volatile("cp.async.wait_group %0;\n" :: "n"(NN)); }

// ---------------- fused qkv GEMM + BN + LIF ---------------------------------------
// Tile 128(o) x 128(n); block loops t=0..3 with membrane [128][128] in smem.
// Spikes written directly to g_sq/g_sk/g_sv as bf16.
#define FBM 128
#define FBN 128
#define FBK 64
#define FLDA 72
#define FLDB 136
#define FLDC 132
#define FNT 6
#define FA_ST (FBM * FLDA)                 // 9216
#define FAST (2 * FA_ST)                   // 18432
#define FBST (FBK * FLDB)                  // 8704
#define FSTG (FAST + FBST)                 // 27136 elems
#define FMEM_OFF (3 * FSTG * 2)            // 162816 B
#define FSM (FMEM_OFF + FBM * FBN * 4)     // 228352 B

__global__ __launch_bounds__(256, 1)
void gemm_lif_kernel(const __nv_bfloat16* __restrict__ Ahi,
                     const __nv_bfloat16* __restrict__ Alo,
                     const __nv_bfloat16* __restrict__ Bmat,
                     __nv_bfloat16* __restrict__ oq,
                     __nv_bfloat16* __restrict__ ok,
                     __nv_bfloat16* __restrict__ ov)
{
    extern __shared__ char smem[];
    __nv_bfloat16* Sg = (__nv_bfloat16*)smem;
    float*         Cs = (float*)smem;                  // epilogue staging (aliases stages)
    float*         Vm = (float*)(smem + FMEM_OFF);     // membrane [128][128]

    int o0 = blockIdx.x * FBM;
    int n0 = blockIdx.y * FBN;
    int b  = blockIdx.z;
    int s  = o0 / C_;
    int oc0 = o0 - s * C_;
    __nv_bfloat16* outp = (s == 0) ? oq : (s == 1) ? ok : ov;

    int tid = threadIdx.x;
    int wid = tid >> 5;
    int wm = wid & 1;          // 2 warps in M (64 each)
    int wn = wid >> 1;         // 4 warps in N (32 each)

    // init membrane
#pragma unroll
    for (int u = 0; u < 16; u++) {
        int e = tid + u * 256;
        *(float4*)(Vm + e * 4) = make_float4(0.f, 0.f, 0.f, 0.f);
    }
    __syncthreads();

#pragma unroll 1
    for (int t = 0; t < T_; t++) {
        const __nv_bfloat16* Bp = Bmat + (size_t)(t * B_ + b) * C_ * N_;

        wmma::fragment<wmma::accumulator, 16, 16, 16, float> acc[4][2];
#pragma unroll
        for (int i = 0; i < 4; i++)
#pragma unroll
            for (int j = 0; j < 2; j++) wmma::fill_fragment(acc[i][j], 0.f);

        auto fill = [&](int kt, int st) {
            __nv_bfloat16* Ah = Sg + st * FSTG;
            __nv_bfloat16* Al = Ah + FA_ST;
            __nv_bfloat16* Bd = Ah + FAST;
            int ka = kt * FBK;
#pragma unroll
            for (int u = 0; u < 4; u++) {            // A hi+lo: 128x64
                int idx = tid + u * 256;
                int r = idx >> 3, c8 = (idx & 7) << 3;
                size_t go = (size_t)(o0 + r) * C_ + ka + c8;
                cpa16(Ah + r * FLDA + c8, Ahi + go);
                cpa16(Al + r * FLDA + c8, Alo + go);
            }
#pragma unroll
            for (int u = 0; u < 4; u++) {            // B: 64x128
                int idx = tid + u * 256;
                int r = idx >> 4, c8 = (idx & 15) << 3;
                cpa16(Bd + r * FLDB + c8, Bp + (size_t)(ka + r) * N_ + n0 + c8);
            }
            cpa_commit();
        };

        fill(0, 0);
        fill(1, 1);
        for (int kt = 0; kt < FNT; kt++) {
            if (kt + 1 < FNT) cpa_wait<1>(); else cpa_wait<0>();
            __syncthreads();
            int st = kt % 3;
            const __nv_bfloat16* Ah = Sg + st * FSTG;
            const __nv_bfloat16* Al = Ah + FA_ST;
            const __nv_bfloat16* Bb = Ah + FAST;
#pragma unroll
            for (int ks = 0; ks < 4; ks++) {
                wmma::fragment<wmma::matrix_b, 16, 16, 16, __nv_bfloat16, wmma::row_major> bfr[2];
#pragma unroll
                for (int j = 0; j < 2; j++)
                    wmma::load_matrix_sync(bfr[j], Bb + (ks * 16) * FLDB + wn * 32 + j * 16, FLDB);
                wmma::fragment<wmma::matrix_a, 16, 16, 16, __nv_bfloat16, wmma::row_major> af[4];
#pragma unroll
                for (int i = 0; i < 4; i++)
                    wmma::load_matrix_sync(af[i], Ah + (wm * 64 + i * 16) * FLDA + ks * 16, FLDA);
#pragma unroll
                for (int i = 0; i < 4; i++)
#pragma unroll
                    for (int j = 0; j < 2; j++)
                        wmma::mma_sync(acc[i][j], af[i], bfr[j], acc[i][j]);
#pragma unroll
                for (int i = 0; i < 4; i++)
                    wmma::load_matrix_sync(af[i], Al + (wm * 64 + i * 16) * FLDA + ks * 16, FLDA);
#pragma unroll
                for (int i = 0; i < 4; i++)
#pragma unroll
                    for (int j = 0; j < 2; j++)
                        wmma::mma_sync(acc[i][j], af[i], bfr[j], acc[i][j]);
            }
            if (kt + 2 < FNT) fill(kt + 2, (kt + 2) % 3);
        }
        __syncthreads();

        // stage accumulators
#pragma unroll
        for (int i = 0; i < 4; i++)
#pragma unroll
            for (int j = 0; j < 2; j++)
                wmma::store_matrix_sync(Cs + (wm * 64 + i * 16) * FLDC + wn * 32 + j * 16,
                                        acc[i][j], FLDC, wmma::mem_row_major);
        __syncthreads();

        // BN shift + LIF + spike write
        {
            size_t obase = (size_t)(t * B_ + b) * C_ * N_;
#pragma unroll
            for (int u = 0; u < 16; u++) {       // 4096 float4 groups
                int e = tid + u * 256;
                int r = e >> 5;
                int c4 = (e & 31) << 2;
                float add = g_bnb[o0 + r];
                float4 y = *(float4*)(Cs + r * FLDC + c4);
                float4 mv = *(float4*)(Vm + r * FBN + c4);
                y.x += add; y.y += add; y.z += add; y.w += add;
                float hh, s0, s1v, s2v, s3v;
                hh = mv.x + (y.x - mv.x) * 0.5f; s0 = (hh >= 1.f) ? 1.f : 0.f; mv.x = (hh >= 1.f) ? 0.f : hh;
                hh = mv.y + (y.y - mv.y) * 0.5f; s1v = (hh >= 1.f) ? 1.f : 0.f; mv.y = (hh >= 1.f) ? 0.f : hh;
                hh = mv.z + (y.z - mv.z) * 0.5f; s2v = (hh >= 1.f) ? 1.f : 0.f; mv.z = (hh >= 1.f) ? 0.f : hh;
                hh = mv.w + (y.w - mv.w) * 0.5f; s3v = (hh >= 1.f) ? 1.f : 0.f; mv.w = (hh >= 1.f) ? 0.f : hh;
                *(float4*)(Vm + r * FBN + c4) = mv;
                __nv_bfloat162 p0 = __floats2bfloat162_rn(s0, s1v);
                __nv_bfloat162 p1 = __floats2bfloat162_rn(s2v, s3v);
                uint2 w;
                w.x = *(unsigned int*)&p0;
                w.y = *(unsigned int*)&p1;
                *(uint2*)(outp + obase + (size_t)(oc0 + r) * N_ + n0 + c4) = w;
            }
        }
        __syncthreads();
    }
}

// ---------------- proj GEMM + folded BN (identical to R8) -------------------------
#define GBM 128
#define GBN 256
#define GBK 64
#define LDA 72
#define LDB 264
#define LDC 260
#define NT_ 6
#define A_ST (GBM * LDA)
#define AST (2 * A_ST)
#define BST (GBK * LDB)
#define STG_ (AST + BST)
#define GSM (3 * STG_ * 2)                // 211968 B

__global__ __launch_bounds__(256, 1)
void gemm_bn_kernel(const __nv_bfloat16* __restrict__ Ahi,
                    const __nv_bfloat16* __restrict__ Alo,
                    const __nv_bfloat16* __restrict__ Bmat,
                    int ldo, int bnoff, float* __restrict__ out)
{
    extern __shared__ char smem[];
    __nv_bfloat16* Sg = (__nv_bfloat16*)smem;
    float*         Cs = (float*)smem;

    int o0 = blockIdx.x * GBM;
    int tb = blockIdx.z;
    const __nv_bfloat16* Bp = Bmat + (size_t)tb * C_ * N_;
    int tid = threadIdx.x;
    int wid = tid >> 5;
    int wm = wid & 1;
    int wn = wid >> 1;

    wmma::fragment<wmma::accumulator, 16, 16, 16, float> acc[4][4];
#pragma unroll
    for (int i = 0; i < 4; i++)
#pragma unroll
        for (int j = 0; j < 4; j++) wmma::fill_fragment(acc[i][j], 0.f);

    auto fill = [&](int kt, int st) {
        __nv_bfloat16* Ah = Sg + st * STG_;
        __nv_bfloat16* Al = Ah + A_ST;
        __nv_bfloat16* Bd = Ah + AST;
        int ka = kt * GBK;
#pragma unroll
        for (int u = 0; u < 4; u++) {
            int idx = tid + u * 256;
            int r = idx >> 3, c8 = (idx & 7) << 3;
            size_t go = (size_t)(o0 + r) * C_ + ka + c8;
            cpa16(Ah + r * LDA + c8, Ahi + go);
            cpa16(Al + r * LDA + c8, Alo + go);
        }
#pragma unroll
        for (int u = 0; u < 8; u++) {
            int idx = tid + u * 256;
            int r = idx >> 5, c8 = (idx & 31) << 3;
            cpa16(Bd + r * LDB + c8, Bp + (size_t)(ka + r) * N_ + c8);
        }
        cpa_commit();
    };

    fill(0, 0);
    fill(1, 1);
    for (int kt = 0; kt < NT_; kt++) {
        if (kt + 1 < NT_) cpa_wait<1>(); else cpa_wait<0>();
        __syncthreads();
        int st = kt % 3;
        const __nv_bfloat16* Ah = Sg + st * STG_;
        const __nv_bfloat16* Al = Ah + A_ST;
        const __nv_bfloat16* Bb = Ah + AST;
#pragma unroll
        for (int ks = 0; ks < 4; ks++) {
            wmma::fragment<wmma::matrix_b, 16, 16, 16, __nv_bfloat16, wmma::row_major> bfr[4];
#pragma unroll
            for (int j = 0; j < 4; j++)
                wmma::load_matrix_sync(bfr[j], Bb + (ks * 16) * LDB + wn * 64 + j * 16, LDB);
            wmma::fragment<wmma::matrix_a, 16, 16, 16, __nv_bfloat16, wmma::row_major> af[4];
#pragma unroll
            for (int i = 0; i < 4; i++)
                wmma::load_matrix_sync(af[i], Ah + (wm * 64 + i * 16) * LDA + ks * 16, LDA);
#pragma unroll
            for (int i = 0; i < 4; i++)
#pragma unroll
                for (int j = 0; j < 4; j++)
                    wmma::mma_sync(acc[i][j], af[i], bfr[j], acc[i][j]);
#pragma unroll
            for (int i = 0; i < 4; i++)
                wmma::load_matrix_sync(af[i], Al + (wm * 64 + i * 16) * LDA + ks * 16, LDA);
#pragma unroll
            for (int i = 0; i < 4; i++)
#pragma unroll
                for (int j = 0; j < 4; j++)
                    wmma::mma_sync(acc[i][j], af[i], bfr[j], acc[i][j]);
        }
        if (kt + 2 < NT_) fill(kt + 2, (kt + 2) % 3);
    }
    __syncthreads();

#pragma unroll
    for (int i = 0; i < 4; i++)
#pragma unroll
        for (int j = 0; j < 4; j++)
            wmma::store_matrix_sync(Cs + (wm * 64 + i * 16) * LDC + wn * 64 + j * 16,
                                    acc[i][j], LDC, wmma::mem_row_major);
    __syncthreads();

#pragma unroll
    for (int u = 0; u < 32; u++) {
        int e = tid + u * 256;
        int r = e >> 6;
        int c4 = (e & 63) << 2;
        int o = o0 + r;
        float add = g_bnb[bnoff + o];
        float4 val = *(float4*)(Cs + r * LDC + c4);
        val.x += add; val.y += add; val.z += add; val.w += add;
        *(float4*)(out + ((size_t)tb * ldo + o) * N_ + c4) = val;
    }
}

// ---------------- tensor-core attention (identical to R10) ------------------------
#define LDQ 264
#define LDSF 68
#define LDS2 72
#define LDO 68
#define AQ_  0
#define AK_  (64 * LDQ * 2)
#define AV_  (2 * 64 * LDQ * 2)
#define ASF_ (3 * 64 * LDQ * 2)
#define AST2 (ASF_ + 256 * LDSF * 4)
#define ASM_ (AST2 + 256 * LDS2 * 2)           // 207872 B

__global__ __launch_bounds__(256)
void attn_kernel(const __nv_bfloat16* __restrict__ q, const __nv_bfloat16* __restrict__ k,
                 const __nv_bfloat16* __restrict__ v, float* __restrict__ out)
{
    extern __shared__ char smraw[];
    __nv_bfloat16* Qs = (__nv_bfloat16*)(smraw + AQ_);
    __nv_bfloat16* Ks = (__nv_bfloat16*)(smraw + AK_);
    __nv_bfloat16* Vs = (__nv_bfloat16*)(smraw + AV_);
    float*         Sfp = (float*)(smraw + ASF_);
    float*         Osm = (float*)(smraw + ASF_);
    __nv_bfloat16* Stb = (__nv_bfloat16*)(smraw + AST2);

    int blk = blockIdx.x;
    int tb = blk >> 3, h = blk & 7;
    size_t base = ((size_t)tb * C_ + h * D_) * N_;
    int tid = threadIdx.x;
    int wid = tid >> 5;

    const __nv_bfloat16* srcs[3] = { q + base, k + base, v + base };
    __nv_bfloat16* dsts[3] = { Qs, Ks, Vs };
#pragma unroll
    for (int mtx = 0; mtx < 3; mtx++) {
#pragma unroll
        for (int u = 0; u < 6; u++) {
            int idx = tid + u * 256;
            int r = idx >> 5, col = (idx & 31) << 3;
            *(uint4*)(dsts[mtx] + r * LDQ + col) = *(const uint4*)(srcs[mtx] + (size_t)r * N_ + col);
        }
#pragma unroll
        for (int u = 0; u < 2; u++) {
            int idx = tid + u * 256;
            int r = 48 + (idx >> 5), col = (idx & 31) << 3;
            *(uint4*)(dsts[mtx] + r * LDQ + col) = make_uint4(0, 0, 0, 0);
        }
    }
    __syncthreads();

#pragma unroll 1
    for (int nt = 0; nt < 4; nt++) {
        int n0 = nt * 64;

        {
            int wm2 = wid & 3;
            int wn2 = wid >> 2;
            wmma::fragment<wmma::accumulator, 16, 16, 16, float> sacc[4][2];
#pragma unroll
            for (int i = 0; i < 4; i++)
#pragma unroll
                for (int j = 0; j < 2; j++) wmma::fill_fragment(sacc[i][j], 0.f);
#pragma unroll
            for (int dk = 0; dk < 64; dk += 16) {
                wmma::fragment<wmma::matrix_a, 16, 16, 16, __nv_bfloat16, wmma::col_major> ak[4];
                wmma::fragment<wmma::matrix_b, 16, 16, 16, __nv_bfloat16, wmma::row_major> bq[2];
#pragma unroll
                for (int i = 0; i < 4; i++)
                    wmma::load_matrix_sync(ak[i], Ks + dk * LDQ + wm2 * 64 + i * 16, LDQ);
#pragma unroll
                for (int j = 0; j < 2; j++)
                    wmma::load_matrix_sync(bq[j], Qs + dk * LDQ + n0 + wn2 * 32 + j * 16, LDQ);
#pragma unroll
                for (int i = 0; i < 4; i++)
#pragma unroll
                    for (int j = 0; j < 2; j++)
                        wmma::mma_sync(sacc[i][j], ak[i], bq[j], sacc[i][j]);
            }
#pragma unroll
            for (int i = 0; i < 4; i++)
#pragma unroll
                for (int j = 0; j < 2; j++)
                    wmma::store_matrix_sync(Sfp + (wm2 * 64 + i * 16) * LDSF + wn2 * 32 + j * 16,
                                            sacc[i][j], LDSF, wmma::mem_row_major);
        }
        __syncthreads();

#pragma unroll
        for (int u = 0; u < 16; u++) {
            int idx = tid + u * 256;
            int m = idx >> 4, c4 = (idx & 15) << 2;
            float4 val = *(float4*)(Sfp + m * LDSF + c4);
            __nv_bfloat162 p0 = __floats2bfloat162_rn(val.x, val.y);
            __nv_bfloat162 p1 = __floats2bfloat162_rn(val.z, val.w);
            uint2 w;
            w.x = *(unsigned int*)&p0;
            w.y = *(unsigned int*)&p1;
            *(uint2*)(Stb + m * LDS2 + c4) = w;
        }
        __syncthreads();

        {
            int dr = wid & 1;
            int nc = wid >> 1;
            wmma::fragment<wmma::accumulator, 16, 16, 16, float> oacc[2];
#pragma unroll
            for (int i = 0; i < 2; i++) wmma::fill_fragment(oacc[i], 0.f);
#pragma unroll
            for (int m = 0; m < 256; m += 16) {
                wmma::fragment<wmma::matrix_a, 16, 16, 16, __nv_bfloat16, wmma::row_major> av[2];
                wmma::fragment<wmma::matrix_b, 16, 16, 16, __nv_bfloat16, wmma::row_major> bs;
#pragma unroll
                for (int i = 0; i < 2; i++)
                    wmma::load_matrix_sync(av[i], Vs + (dr * 32 + i * 16) * LDQ + m, LDQ);
                wmma::load_matrix_sync(bs, Stb + m * LDS2 + nc * 16, LDS2);
#pragma unroll
                for (int i = 0; i < 2; i++)
                    wmma::mma_sync(oacc[i], av[i], bs, oacc[i]);
            }
#pragma unroll
            for (int i = 0; i < 2; i++)
                wmma::store_matrix_sync(Osm + (dr * 32 + i * 16) * LDO + nc * 16,
                                        oacc[i], LDO, wmma::mem_row_major);
        }
        __syncthreads();

#pragma unroll
        for (int u = 0; u < 3; u++) {
            int e = tid + u * 256;
            int d = e >> 4, c4 = (e & 15) << 2;
            float4 val = *(float4*)(Osm + d * LDO + c4);
            val.x *= 0.125f; val.y *= 0.125f; val.z *= 0.125f; val.w *= 0.125f;
            *(float4*)(out + base + (size_t)d * N_ + n0 + c4) = val;
        }
        __syncthreads();
    }
}

// ---------------- launch ----------------------------------------------------------
extern "C" void kernel_launch(void* const* d_in, const int* in_sizes, int n_in,
                              void* d_out, int out_size)
{
    const float* x   = (const float*)d_in[0];
    const float* qw  = (const float*)d_in[2];
    const float* qg  = (const float*)d_in[3];
    const float* qb  = (const float*)d_in[4];
    const float* qm  = (const float*)d_in[5];
    const float* qv  = (const float*)d_in[6];
    const float* kw  = (const float*)d_in[7];
    const float* kg  = (const float*)d_in[8];
    const float* kb  = (const float*)d_in[9];
    const float* km  = (const float*)d_in[10];
    const float* kv  = (const float*)d_in[11];
    const float* vw  = (const float*)d_in[12];
    const float* vg  = (const float*)d_in[13];
    const float* vb  = (const float*)d_in[14];
    const float* vm  = (const float*)d_in[15];
    const float* vv  = (const float*)d_in[16];
    const float* pw  = (const float*)d_in[17];
    const float* pbias = (const float*)d_in[18];
    const float* pg  = (const float*)d_in[19];
    const float* pb  = (const float*)d_in[20];
    const float* pm  = (const float*)d_in[21];
    const float* pv  = (const float*)d_in[22];

    void *ps1, *psq, *psk, *psv, *ps2, *pya, *phi, *plo;
    cudaGetSymbolAddress(&ps1, g_s1);
    cudaGetSymbolAddress(&psq, g_sq);
    cudaGetSymbolAddress(&psk, g_sk);
    cudaGetSymbolAddress(&psv, g_sv);
    cudaGetSymbolAddress(&ps2, g_s2);
    cudaGetSymbolAddress(&pya, g_ya);
    cudaGetSymbolAddress(&phi, g_whi);
    cudaGetSymbolAddress(&plo, g_wlo);
    __nv_bfloat16* s1  = (__nv_bfloat16*)ps1;
    __nv_bfloat16* sq  = (__nv_bfloat16*)psq;
    __nv_bfloat16* sk  = (__nv_bfloat16*)psk;
    __nv_bfloat16* sv  = (__nv_bfloat16*)psv;
    __nv_bfloat16* s2  = (__nv_bfloat16*)ps2;
    float*         ya  = (float*)pya;
    __nv_bfloat16* whi = (__nv_bfloat16*)phi;
    __nv_bfloat16* wlo = (__nv_bfloat16*)plo;

    cudaFuncSetAttribute(gemm_lif_kernel, cudaFuncAttributeMaxDynamicSharedMemorySize, FSM);
    cudaFuncSetAttribute(gemm_bn_kernel, cudaFuncAttributeMaxDynamicSharedMemorySize, GSM);
    cudaFuncSetAttribute(attn_kernel, cudaFuncAttributeMaxDynamicSharedMemorySize, ASM_);

    // prep: BN fold first (wconv consumes g_bns)
    bnfold_kernel<<<6, 256>>>(qg, qb, qm, qv, kg, kb, km, kv,
                              vg, vb, vm, vv, pg, pb, pm, pv, pbias);
    wconv_kernel<<<(4 * C_ * C_ + 255) / 256, 256>>>(qw, kw, vw, pw);
    // proj_lif on input
    lif_kernel<<<BCN_ / 256, 256>>>(x, s1);
    // fused q,k,v GEMM + BN + LIF: (9 o-tiles, 2 n-tiles, 32 b), t-loop inside
    gemm_lif_kernel<<<dim3(M3_ / FBM, N_ / FBN, B_), 256, FSM>>>(
        whi, wlo, s1, sq, sk, sv);
    // bf16 tensor attention -> fp32
    attn_kernel<<<TBH_, 256, ASM_>>>(sq, sk, sv, ya);
    // attn_lif
    lif_kernel<<<BCN_ / 256, 256>>>(ya, s2);
    // proj GEMM + bias + BN -> final output
    gemm_bn_kernel<<<dim3(C_ / GBM, 1, TB_), 256, GSM>>>(
        whi + 3 * C_ * C_, wlo + 3 * C_ * C_, s2, C_, 3 * C_, (float*)d_out);
}

// round 12
// speedup vs baseline: 1.3042x; 1.0118x over previous
#include <cuda_runtime.h>
#include <cuda_bf16.h>
#include <mma.h>
#include <cstdint>

using namespace nvcuda;

#define T_   4
#define B_   32
#define C_   384
#define N_   256
#define H_   8
#define D_   48
#define TB_  (T_ * B_)
#define TBH_ (TB_ * H_)
#define BCN_ (B_ * C_ * N_)      // 3,145,728
#define TOT_ (T_ * BCN_)         // 12,582,912
#define M3_  (3 * C_)            // 1152

// ---------------- scratch (device globals) ----------------------------------------
__device__ __nv_bfloat16 g_s1[TOT_];           // spikes after lif1   [tb][c][n]
__device__ __nv_bfloat16 g_sq[TOT_];           // q spikes            [tb][c][n]
__device__ __nv_bfloat16 g_sk[TOT_];
__device__ __nv_bfloat16 g_sv[TOT_];
__device__ __nv_bfloat16 g_s2[TOT_];           // attn-lif spikes
__device__ float         g_ya[TOT_];           // attention out fp32  [tb][c][n]
__device__ __nv_bfloat16 g_whi[4 * C_ * C_];   // hi bf16 of BN-scaled weights
__device__ __nv_bfloat16 g_wlo[4 * C_ * C_];   // lo residual
__device__ float         g_bns[4 * C_];        // folded BN scale
__device__ float         g_bnb[4 * C_];        // folded BN shift

// ---------------- prep ------------------------------------------------------------
__global__ void bnfold_kernel(const float* qg, const float* qb, const float* qm, const float* qv,
                              const float* kg, const float* kb, const float* km, const float* kv,
                              const float* vg, const float* vb, const float* vm, const float* vv,
                              const float* pg, const float* pb, const float* pm, const float* pv,
                              const float* pbias)
{
    int i = blockIdx.x * 256 + threadIdx.x;
    if (i >= 4 * C_) return;
    int s = i / C_, c = i - s * C_;
    const float *G, *Bt, *M, *V;
    if      (s == 0) { G = qg; Bt = qb; M = qm; V = qv; }
    else if (s == 1) { G = kg; Bt = kb; M = km; V = kv; }
    else if (s == 2) { G = vg; Bt = vb; M = vm; V = vv; }
    else             { G = pg; Bt = pb; M = pm; V = pv; }
    float inv = G[c] / sqrtf(V[c] + 1e-5f);
    float add = Bt[c] - M[c] * inv;
    if (s == 3) add += pbias[c] * inv;
    g_bns[i] = inv;
    g_bnb[i] = add;
}

__global__ void wconv_kernel(const float* __restrict__ w0, const float* __restrict__ w1,
                             const float* __restrict__ w2, const float* __restrict__ w3)
{
    int i = blockIdx.x * 256 + threadIdx.x;
    if (i >= 4 * C_ * C_) return;
    int s = i / (C_ * C_);
    int j = i - s * (C_ * C_);
    int o = j / C_;
    const float* w = (s == 0) ? w0 : (s == 1) ? w1 : (s == 2) ? w2 : w3;
    float val = w[j] * g_bns[s * C_ + o];
    __nv_bfloat16 hi = __float2bfloat16(val);
    g_whi[i] = hi;
    g_wlo[i] = __float2bfloat16(val - __bfloat162float(hi));
}

// ---------------- LIF -------------------------------------------------------------
__global__ void lif_kernel(const float* __restrict__ xin, __nv_bfloat16* __restrict__ sout)
{
    int i = blockIdx.x * 256 + threadIdx.x;
    if (i >= BCN_) return;
    float v = 0.f;
#pragma unroll
    for (int t = 0; t < T_; t++) {
        float xv = xin[(size_t)t * BCN_ + i];
        float h = v + (xv - v) * 0.5f;
        bool sp = (h >= 1.0f);
        sout[(size_t)t * BCN_ + i] = __float2bfloat16(sp ? 1.f : 0.f);
        v = sp ? 0.f : h;
    }
}

// ---------------- cp.async helpers ------------------------------------------------
__device__ __forceinline__ void cpa16(void* s, const void* g)
{
    unsigned int sa = (unsigned int)__cvta_generic_to_shared(s);
    asm volatile("cp.async.cg.shared.global [%0], [%1], 16;\n" :: "r"(sa), "l"(g));
}
__device__ __forceinline__ void cpa_commit() { asm volatile("cp.async.commit_group;\n"); }
template <int NN>
__device__ __forceinline__ void cpa_wait() { asm volatile("cp.async.wait_group %0;\n" :: "n"(NN)); }

// ---------------- fused qkv GEMM + BN + LIF (tile 128x256, GBK=32, 2-stage) -------
// Membrane [128][256] fp32 resident in smem across the t-loop.
#define FBM 128
#define FBN 256
#define FBK 32
#define FLDA 40                            // 32 + 8 pad
#define FLDB 264                           // 256 + 8 pad
#define FLDC 132                           // 128 + 4 pad (fp32, per half)
#define FNT 12                             // C_/FBK
#define FA_ST (FBM * FLDA)                 // 5120 elems
#define FAST (2 * FA_ST)                   // hi + lo: 10240
#define FBST (FBK * FLDB)                  // 8448
#define FSTG (FAST + FBST)                 // 18688 elems = 37376 B
#define FMEM_OFF (2 * FSTG * 2)            // 74752 B
#define FSM (FMEM_OFF + FBM * FBN * 4)     // 205824 B

__global__ __launch_bounds__(256, 1)
void gemm_lif_kernel(const __nv_bfloat16* __restrict__ Ahi,
                     const __nv_bfloat16* __restrict__ Alo,
                     const __nv_bfloat16* __restrict__ Bmat,
                     __nv_bfloat16* __restrict__ oq,
                     __nv_bfloat16* __restrict__ ok,
                     __nv_bfloat16* __restrict__ ov)
{
    extern __shared__ char smem[];
    __nv_bfloat16* Sg = (__nv_bfloat16*)smem;
    float*         Cs = (float*)smem;                  // epilogue half staging
    float*         Vm = (float*)(smem + FMEM_OFF);     // membrane [128][256]

    int o0 = blockIdx.x * FBM;
    int b  = blockIdx.z;
    int s  = o0 / C_;
    int oc0 = o0 - s * C_;
    __nv_bfloat16* outp = (s == 0) ? oq : (s == 1) ? ok : ov;

    int tid = threadIdx.x;
    int wid = tid >> 5;
    int wm = wid & 1;          // 2 warps in M (64 rows each)
    int wn = wid >> 1;         // 4 warps in N (64 cols each)

    // init membrane
#pragma unroll
    for (int u = 0; u < 32; u++) {
        int e = tid + u * 256;
        *(float4*)(Vm + e * 4) = make_float4(0.f, 0.f, 0.f, 0.f);
    }
    __syncthreads();

#pragma unroll 1
    for (int t = 0; t < T_; t++) {
        const __nv_bfloat16* Bp = Bmat + (size_t)(t * B_ + b) * C_ * N_;

        wmma::fragment<wmma::accumulator, 16, 16, 16, float> acc[4][4];
#pragma unroll
        for (int i = 0; i < 4; i++)
#pragma unroll
            for (int j = 0; j < 4; j++) wmma::fill_fragment(acc[i][j], 0.f);

        auto fill = [&](int kt, int st) {
            __nv_bfloat16* Ah = Sg + st * FSTG;
            __nv_bfloat16* Al = Ah + FA_ST;
            __nv_bfloat16* Bd = Ah + FAST;
            int ka = kt * FBK;
#pragma unroll
            for (int u = 0; u < 2; u++) {            // A hi+lo: 128x32 (512 chunks each)
                int idx = tid + u * 256;
                int r = idx >> 2, c8 = (idx & 3) << 3;
                size_t go = (size_t)(o0 + r) * C_ + ka + c8;
                cpa16(Ah + r * FLDA + c8, Ahi + go);
                cpa16(Al + r * FLDA + c8, Alo + go);
            }
#pragma unroll
            for (int u = 0; u < 4; u++) {            // B: 32x256 (1024 chunks)
                int idx = tid + u * 256;
                int r = idx >> 5, c8 = (idx & 31) << 3;
                cpa16(Bd + r * FLDB + c8, Bp + (size_t)(ka + r) * N_ + c8);
            }
            cpa_commit();
        };

        fill(0, 0);
        fill(1, 1);
        for (int kt = 0; kt < FNT; kt++) {
            if (kt + 1 < FNT) cpa_wait<1>(); else cpa_wait<0>();
            __syncthreads();
            int st = kt & 1;
            const __nv_bfloat16* Ah = Sg + st * FSTG;
            const __nv_bfloat16* Al = Ah + FA_ST;
            const __nv_bfloat16* Bb = Ah + FAST;
#pragma unroll
            for (int ks = 0; ks < 2; ks++) {
                wmma::fragment<wmma::matrix_b, 16, 16, 16, __nv_bfloat16, wmma::row_major> bfr[4];
#pragma unroll
                for (int j = 0; j < 4; j++)
                    wmma::load_matrix_sync(bfr[j], Bb + (ks * 16) * FLDB + wn * 64 + j * 16, FLDB);
                wmma::fragment<wmma::matrix_a, 16, 16, 16, __nv_bfloat16, wmma::row_major> af[4];
#pragma unroll
                for (int i = 0; i < 4; i++)
                    wmma::load_matrix_sync(af[i], Ah + (wm * 64 + i * 16) * FLDA + ks * 16, FLDA);
#pragma unroll
                for (int i = 0; i < 4; i++)
#pragma unroll
                    for (int j = 0; j < 4; j++)
                        wmma::mma_sync(acc[i][j], af[i], bfr[j], acc[i][j]);
#pragma unroll
                for (int i = 0; i < 4; i++)
                    wmma::load_matrix_sync(af[i], Al + (wm * 64 + i * 16) * FLDA + ks * 16, FLDA);
#pragma unroll
                for (int i = 0; i < 4; i++)
#pragma unroll
                    for (int j = 0; j < 4; j++)
                        wmma::mma_sync(acc[i][j], af[i], bfr[j], acc[i][j]);
            }
            __syncthreads();           // all warps done reading stage st
            if (kt + 2 < FNT) fill(kt + 2, st);
        }
        __syncthreads();               // stage reads done before Cs overwrite

        // epilogue in two 128-col halves (Cs fits the stage alias area)
        size_t obase = (size_t)(t * B_ + b) * C_ * N_;
#pragma unroll 1
        for (int hhalf = 0; hhalf < 2; hhalf++) {
            if ((wn >> 1) == hhalf) {
                int wnl = wn & 1;      // 0..1 within half
#pragma unroll
                for (int i = 0; i < 4; i++)
#pragma unroll
                    for (int j = 0; j < 4; j++)
                        wmma::store_matrix_sync(Cs + (wm * 64 + i * 16) * FLDC + wnl * 64 + j * 16,
                                                acc[i][j], FLDC, wmma::mem_row_major);
            }
            __syncthreads();
#pragma unroll
            for (int u = 0; u < 16; u++) {       // 4096 float4 (128x128)
                int e = tid + u * 256;
                int r = e >> 5;
                int c4 = (e & 31) << 2;
                int cg = hhalf * 128 + c4;
                float add = g_bnb[o0 + r];
                float4 y = *(float4*)(Cs + r * FLDC + c4);
                float4 mv = *(float4*)(Vm + r * FBN + cg);
                y.x += add; y.y += add; y.z += add; y.w += add;
                float hh, s0, s1v, s2v, s3v;
                hh = mv.x + (y.x - mv.x) * 0.5f; s0 = (hh >= 1.f) ? 1.f : 0.f; mv.x = (hh >= 1.f) ? 0.f : hh;
                hh = mv.y + (y.y - mv.y) * 0.5f; s1v = (hh >= 1.f) ? 1.f : 0.f; mv.y = (hh >= 1.f) ? 0.f : hh;
                hh = mv.z + (y.z - mv.z) * 0.5f; s2v = (hh >= 1.f) ? 1.f : 0.f; mv.z = (hh >= 1.f) ? 0.f : hh;
                hh = mv.w + (y.w - mv.w) * 0.5f; s3v = (hh >= 1.f) ? 1.f : 0.f; mv.w = (hh >= 1.f) ? 0.f : hh;
                *(float4*)(Vm + r * FBN + cg) = mv;
                __nv_bfloat162 p0 = __floats2bfloat162_rn(s0, s1v);
                __nv_bfloat162 p1 = __floats2bfloat162_rn(s2v, s3v);
                uint2 w;
                w.x = *(unsigned int*)&p0;
                w.y = *(unsigned int*)&p1;
                *(uint2*)(outp + obase + (size_t)(oc0 + r) * N_ + cg) = w;
            }
            __syncthreads();
        }
    }
}

// ---------------- proj GEMM + folded BN (identical to R8) -------------------------
#define GBM 128
#define GBN 256
#define GBK 64
#define LDA 72
#define LDB 264
#define LDC 260
#define NT_ 6
#define A_ST (GBM * LDA)
#define AST (2 * A_ST)
#define BST (GBK * LDB)
#define STG_ (AST + BST)
#define GSM (3 * STG_ * 2)                // 211968 B

__global__ __launch_bounds__(256, 1)
void gemm_bn_kernel(const __nv_bfloat16* __restrict__ Ahi,
                    const __nv_bfloat16* __restrict__ Alo,
                    const __nv_bfloat16* __restrict__ Bmat,
                    int ldo, int bnoff, float* __restrict__ out)
{
    extern __shared__ char smem[];
    __nv_bfloat16* Sg = (__nv_bfloat16*)smem;
    float*         Cs = (float*)smem;

    int o0 = blockIdx.x * GBM;
    int tb = blockIdx.z;
    const __nv_bfloat16* Bp = Bmat + (size_t)tb * C_ * N_;
    int tid = threadIdx.x;
    int wid = tid >> 5;
    int wm = wid & 1;
    int wn = wid >> 1;

    wmma::fragment<wmma::accumulator, 16, 16, 16, float> acc[4][4];
#pragma unroll
    for (int i = 0; i < 4; i++)
#pragma unroll
        for (int j = 0; j < 4; j++) wmma::fill_fragment(acc[i][j], 0.f);

    auto fill = [&](int kt, int st) {
        __nv_bfloat16* Ah = Sg + st * STG_;
        __nv_bfloat16* Al = Ah + A_ST;
        __nv_bfloat16* Bd = Ah + AST;
        int ka = kt * GBK;
#pragma unroll
        for (int u = 0; u < 4; u++) {
            int idx = tid + u * 256;
            int r = idx >> 3, c8 = (idx & 7) << 3;
            size_t go = (size_t)(o0 + r) * C_ + ka + c8;
            cpa16(Ah + r * LDA + c8, Ahi + go);
            cpa16(Al + r * LDA + c8, Alo + go);
        }
#pragma unroll
        for (int u = 0; u < 8; u++) {
            int idx = tid + u * 256;
            int r = idx >> 5, c8 = (idx & 31) << 3;
            cpa16(Bd + r * LDB + c8, Bp + (size_t)(ka + r) * N_ + c8);
        }
        cpa_commit();
    };

    fill(0, 0);
    fill(1, 1);
    for (int kt = 0; kt < NT_; kt++) {
        if (kt + 1 < NT_) cpa_wait<1>(); else cpa_wait<0>();
        __syncthreads();
        int st = kt % 3;
        const __nv_bfloat16* Ah = Sg + st * STG_;
        const __nv_bfloat16* Al = Ah + A_ST;
        const __nv_bfloat16* Bb = Ah + AST;
#pragma unroll
        for (int ks = 0; ks < 4; ks++) {
            wmma::fragment<wmma::matrix_b, 16, 16, 16, __nv_bfloat16, wmma::row_major> bfr[4];
#pragma unroll
            for (int j = 0; j < 4; j++)
                wmma::load_matrix_sync(bfr[j], Bb + (ks * 16) * LDB + wn * 64 + j * 16, LDB);
            wmma::fragment<wmma::matrix_a, 16, 16, 16, __nv_bfloat16, wmma::row_major> af[4];
#pragma unroll
            for (int i = 0; i < 4; i++)
                wmma::load_matrix_sync(af[i], Ah + (wm * 64 + i * 16) * LDA + ks * 16, LDA);
#pragma unroll
            for (int i = 0; i < 4; i++)
#pragma unroll
                for (int j = 0; j < 4; j++)
                    wmma::mma_sync(acc[i][j], af[i], bfr[j], acc[i][j]);
#pragma unroll
            for (int i = 0; i < 4; i++)
                wmma::load_matrix_sync(af[i], Al + (wm * 64 + i * 16) * LDA + ks * 16, LDA);
#pragma unroll
            for (int i = 0; i < 4; i++)
#pragma unroll
                for (int j = 0; j < 4; j++)
                    wmma::mma_sync(acc[i][j], af[i], bfr[j], acc[i][j]);
        }
        if (kt + 2 < NT_) fill(kt + 2, (kt + 2) % 3);
    }
    __syncthreads();

#pragma unroll
    for (int i = 0; i < 4; i++)
#pragma unroll
        for (int j = 0; j < 4; j++)
            wmma::store_matrix_sync(Cs + (wm * 64 + i * 16) * LDC + wn * 64 + j * 16,
                                    acc[i][j], LDC, wmma::mem_row_major);
    __syncthreads();

#pragma unroll
    for (int u = 0; u < 32; u++) {
        int e = tid + u * 256;
        int r = e >> 6;
        int c4 = (e & 63) << 2;
        int o = o0 + r;
        float add = g_bnb[bnoff + o];
        float4 val = *(float4*)(Cs + r * LDC + c4);
        val.x += add; val.y += add; val.z += add; val.w += add;
        *(float4*)(out + ((size_t)tb * ldo + o) * N_ + c4) = val;
    }
}

// ---------------- tensor-core attention (dk<48; no Q/K padding needed) ------------
#define LDQ 264
#define LDSF 68
#define LDS2 72
#define LDO 68
#define AQ_  0
#define AK_  (64 * LDQ * 2)
#define AV_  (2 * 64 * LDQ * 2)
#define ASF_ (3 * 64 * LDQ * 2)
#define AST2 (ASF_ + 256 * LDSF * 4)
#define ASM_ (AST2 + 256 * LDS2 * 2)           // 207872 B

__global__ __launch_bounds__(256)
void attn_kernel(const __nv_bfloat16* __restrict__ q, const __nv_bfloat16* __restrict__ k,
                 const __nv_bfloat16* __restrict__ v, float* __restrict__ out)
{
    extern __shared__ char smraw[];
    __nv_bfloat16* Qs = (__nv_bfloat16*)(smraw + AQ_);
    __nv_bfloat16* Ks = (__nv_bfloat16*)(smraw + AK_);
    __nv_bfloat16* Vs = (__nv_bfloat16*)(smraw + AV_);
    float*         Sfp = (float*)(smraw + ASF_);
    float*         Osm = (float*)(smraw + ASF_);
    __nv_bfloat16* Stb = (__nv_bfloat16*)(smraw + AST2);

    int blk = blockIdx.x;
    int tb = blk >> 3, h = blk & 7;
    size_t base = ((size_t)tb * C_ + h * D_) * N_;
    int tid = threadIdx.x;
    int wid = tid >> 5;

    const __nv_bfloat16* srcs[3] = { q + base, k + base, v + base };
    __nv_bfloat16* dsts[3] = { Qs, Ks, Vs };
#pragma unroll
    for (int mtx = 0; mtx < 3; mtx++) {
#pragma unroll
        for (int u = 0; u < 6; u++) {
            int idx = tid + u * 256;
            int r = idx >> 5, col = (idx & 31) << 3;
            *(uint4*)(dsts[mtx] + r * LDQ + col) = *(const uint4*)(srcs[mtx] + (size_t)r * N_ + col);
        }
    }
    // zero-pad rows 48..63 of V only (stage 2 reads d up to 64)
#pragma unroll
    for (int u = 0; u < 2; u++) {
        int idx = tid + u * 256;
        int r = 48 + (idx >> 5), col = (idx & 31) << 3;
        *(uint4*)(Vs + r * LDQ + col) = make_uint4(0, 0, 0, 0);
    }
    __syncthreads();

#pragma unroll 1
    for (int nt = 0; nt < 4; nt++) {
        int n0 = nt * 64;

        {
            int wm2 = wid & 3;
            int wn2 = wid >> 2;
            wmma::fragment<wmma::accumulator, 16, 16, 16, float> sacc[4][2];
#pragma unroll
            for (int i = 0; i < 4; i++)
#pragma unroll
                for (int j = 0; j < 2; j++) wmma::fill_fragment(sacc[i][j], 0.f);
#pragma unroll
            for (int dk = 0; dk < 48; dk += 16) {
                wmma::fragment<wmma::matrix_a, 16, 16, 16, __nv_bfloat16, wmma::col_major> ak[4];
                wmma::fragment<wmma::matrix_b, 16, 16, 16, __nv_bfloat16, wmma::row_major> bq[2];
#pragma unroll
                for (int i = 0; i < 4; i++)
                    wmma::load_matrix_sync(ak[i], Ks + dk * LDQ + wm2 * 64 + i * 16, LDQ);
#pragma unroll
                for (int j = 0; j < 2; j++)
                    wmma::load_matrix_sync(bq[j], Qs + dk * LDQ + n0 + wn2 * 32 + j * 16, LDQ);
#pragma unroll
                for (int i = 0; i < 4; i++)
#pragma unroll
                    for (int j = 0; j < 2; j++)
                        wmma::mma_sync(sacc[i][j], ak[i], bq[j], sacc[i][j]);
            }
#pragma unroll
            for (int i = 0; i < 4; i++)
#pragma unroll
                for (int j = 0; j < 2; j++)
                    wmma::store_matrix_sync(Sfp + (wm2 * 64 + i * 16) * LDSF + wn2 * 32 + j * 16,
                                            sacc[i][j], LDSF, wmma::mem_row_major);
        }
        __syncthreads();

#pragma unroll
        for (int u = 0; u < 16; u++) {
            int idx = tid + u * 256;
            int m = idx >> 4, c4 = (idx & 15) << 2;
            float4 val = *(float4*)(Sfp + m * LDSF + c4);
            __nv_bfloat162 p0 = __floats2bfloat162_rn(val.x, val.y);
            __nv_bfloat162 p1 = __floats2bfloat162_rn(val.z, val.w);
            uint2 w;
            w.x = *(unsigned int*)&p0;
            w.y = *(unsigned int*)&p1;
            *(uint2*)(Stb + m * LDS2 + c4) = w;
        }
        __syncthreads();

        {
            int dr = wid & 1;
            int nc = wid >> 1;
            wmma::fragment<wmma::accumulator, 16, 16, 16, float> oacc[2];
#pragma unroll
            for (int i = 0; i < 2; i++) wmma::fill_fragment(oacc[i], 0.f);
#pragma unroll
            for (int m = 0; m < 256; m += 16) {
                wmma::fragment<wmma::matrix_a, 16, 16, 16, __nv_bfloat16, wmma::row_major> av[2];
                wmma::fragment<wmma::matrix_b, 16, 16, 16, __nv_bfloat16, wmma::row_major> bs;
#pragma unroll
                for (int i = 0; i < 2; i++)
                    wmma::load_matrix_sync(av[i], Vs + (dr * 32 + i * 16) * LDQ + m, LDQ);
                wmma::load_matrix_sync(bs, Stb + m * LDS2 + nc * 16, LDS2);
#pragma unroll
                for (int i = 0; i < 2; i++)
                    wmma::mma_sync(oacc[i], av[i], bs, oacc[i]);
            }
#pragma unroll
            for (int i = 0; i < 2; i++)
                wmma::store_matrix_sync(Osm + (dr * 32 + i * 16) * LDO + nc * 16,
                                        oacc[i], LDO, wmma::mem_row_major);
        }
        __syncthreads();

#pragma unroll
        for (int u = 0; u < 3; u++) {
            int e = tid + u * 256;
            int d = e >> 4, c4 = (e & 15) << 2;
            float4 val = *(float4*)(Osm + d * LDO + c4);
            val.x *= 0.125f; val.y *= 0.125f; val.z *= 0.125f; val.w *= 0.125f;
            *(float4*)(out + base + (size_t)d * N_ + n0 + c4) = val;
        }
        __syncthreads();
    }
}

// ---------------- launch ----------------------------------------------------------
extern "C" void kernel_launch(void* const* d_in, const int* in_sizes, int n_in,
                              void* d_out, int out_size)
{
    const float* x   = (const float*)d_in[0];
    const float* qw  = (const float*)d_in[2];
    const float* qg  = (const float*)d_in[3];
    const float* qb  = (const float*)d_in[4];
    const float* qm  = (const float*)d_in[5];
    const float* qv  = (const float*)d_in[6];
    const float* kw  = (const float*)d_in[7];
    const float* kg  = (const float*)d_in[8];
    const float* kb  = (const float*)d_in[9];
    const float* km  = (const float*)d_in[10];
    const float* kv  = (const float*)d_in[11];
    const float* vw  = (const float*)d_in[12];
    const float* vg  = (const float*)d_in[13];
    const float* vb  = (const float*)d_in[14];
    const float* vm  = (const float*)d_in[15];
    const float* vv  = (const float*)d_in[16];
    const float* pw  = (const float*)d_in[17];
    const float* pbias = (const float*)d_in[18];
    const float* pg  = (const float*)d_in[19];
    const float* pb  = (const float*)d_in[20];
    const float* pm  = (const float*)d_in[21];
    const float* pv  = (const float*)d_in[22];

    void *ps1, *psq, *psk, *psv, *ps2, *pya, *phi, *plo;
    cudaGetSymbolAddress(&ps1, g_s1);
    cudaGetSymbolAddress(&psq, g_sq);
    cudaGetSymbolAddress(&psk, g_sk);
    cudaGetSymbolAddress(&psv, g_sv);
    cudaGetSymbolAddress(&ps2, g_s2);
    cudaGetSymbolAddress(&pya, g_ya);
    cudaGetSymbolAddress(&phi, g_whi);
    cudaGetSymbolAddress(&plo, g_wlo);
    __nv_bfloat16* s1  = (__nv_bfloat16*)ps1;
    __nv_bfloat16* sq  = (__nv_bfloat16*)psq;
    __nv_bfloat16* sk  = (__nv_bfloat16*)psk;
    __nv_bfloat16* sv  = (__nv_bfloat16*)psv;
    __nv_bfloat16* s2  = (__nv_bfloat16*)ps2;
    float*         ya  = (float*)pya;
    __nv_bfloat16* whi = (__nv_bfloat16*)phi;
    __nv_bfloat16* wlo = (__nv_bfloat16*)plo;

    cudaFuncSetAttribute(gemm_lif_kernel, cudaFuncAttributeMaxDynamicSharedMemorySize, FSM);
    cudaFuncSetAttribute(gemm_bn_kernel, cudaFuncAttributeMaxDynamicSharedMemorySize, GSM);
    cudaFuncSetAttribute(attn_kernel, cudaFuncAttributeMaxDynamicSharedMemorySize, ASM_);

    // prep: BN fold first (wconv consumes g_bns)
    bnfold_kernel<<<6, 256>>>(qg, qb, qm, qv, kg, kb, km, kv,
                              vg, vb, vm, vv, pg, pb, pm, pv, pbias);
    wconv_kernel<<<(4 * C_ * C_ + 255) / 256, 256>>>(qw, kw, vw, pw);
    // proj_lif on input
    lif_kernel<<<BCN_ / 256, 256>>>(x, s1);
    // fused q,k,v GEMM + BN + LIF: (9 o-tiles, 1, 32 b), t-loop inside, full-N tile
    gemm_lif_kernel<<<dim3(M3_ / FBM, 1, B_), 256, FSM>>>(
        whi, wlo, s1, sq, sk, sv);
    // bf16 tensor attention -> fp32
    attn_kernel<<<TBH_, 256, ASM_>>>(sq, sk, sv, ya);
    // attn_lif
    lif_kernel<<<BCN_ / 256, 256>>>(ya, s2);
    // proj GEMM + bias + BN -> final output
    gemm_bn_kernel<<<dim3(C_ / GBM, 1, TB_), 256, GSM>>>(
        whi + 3 * C_ * C_, wlo + 3 * C_ * C_, s2, C_, 3 * C_, (float*)d_out);
}

// round 13
// speedup vs baseline: 1.3554x; 1.0393x over previous
#include <cuda_runtime.h>
#include <cuda_bf16.h>
#include <mma.h>
#include <cstdint>

using namespace nvcuda;

#define T_   4
#define B_   32
#define C_   384
#define N_   256
#define H_   8
#define D_   48
#define TB_  (T_ * B_)
#define TBH_ (TB_ * H_)
#define BCN_ (B_ * C_ * N_)      // 3,145,728
#define TOT_ (T_ * BCN_)         // 12,582,912
#define M3_  (3 * C_)            // 1152

// ---------------- scratch (device globals) ----------------------------------------
__device__ __nv_bfloat16 g_s1[TOT_];           // spikes after lif1   [tb][c][n]
__device__ __nv_bfloat16 g_sq[TOT_];           // q spikes            [tb][c][n]
__device__ __nv_bfloat16 g_sk[TOT_];
__device__ __nv_bfloat16 g_sv[TOT_];
__device__ __nv_bfloat16 g_s2[TOT_];           // attn-lif spikes
__device__ float         g_ya[TOT_];           // attention out fp32  [tb][c][n]
__device__ __nv_bfloat16 g_whi[4 * C_ * C_];   // hi bf16 of BN-scaled weights
__device__ __nv_bfloat16 g_wlo[4 * C_ * C_];   // lo residual
__device__ float         g_bns[4 * C_];        // folded BN scale
__device__ float         g_bnb[4 * C_];        // folded BN shift

// ---------------- prep ------------------------------------------------------------
__global__ void bnfold_kernel(const float* qg, const float* qb, const float* qm, const float* qv,
                              const float* kg, const float* kb, const float* km, const float* kv,
                              const float* vg, const float* vb, const float* vm, const float* vv,
                              const float* pg, const float* pb, const float* pm, const float* pv,
                              const float* pbias)
{
    int i = blockIdx.x * 256 + threadIdx.x;
    if (i >= 4 * C_) return;
    int s = i / C_, c = i - s * C_;
    const float *G, *Bt, *M, *V;
    if      (s == 0) { G = qg; Bt = qb; M = qm; V = qv; }
    else if (s == 1) { G = kg; Bt = kb; M = km; V = kv; }
    else if (s == 2) { G = vg; Bt = vb; M = vm; V = vv; }
    else             { G = pg; Bt = pb; M = pm; V = pv; }
    float inv = G[c] / sqrtf(V[c] + 1e-5f);
    float add = Bt[c] - M[c] * inv;
    if (s == 3) add += pbias[c] * inv;
    g_bns[i] = inv;
    g_bnb[i] = add;
}

__global__ void wconv_kernel(const float* __restrict__ w0, const float* __restrict__ w1,
                             const float* __restrict__ w2, const float* __restrict__ w3)
{
    int i = blockIdx.x * 256 + threadIdx.x;
    if (i >= 4 * C_ * C_) return;
    int s = i / (C_ * C_);
    int j = i - s * (C_ * C_);
    int o = j / C_;
    const float* w = (s == 0) ? w0 : (s == 1) ? w1 : (s == 2) ? w2 : w3;
    float val = w[j] * g_bns[s * C_ + o];
    __nv_bfloat16 hi = __float2bfloat16(val);
    g_whi[i] = hi;
    g_wlo[i] = __float2bfloat16(val - __bfloat162float(hi));
}

// ---------------- LIF -------------------------------------------------------------
__global__ void lif_kernel(const float* __restrict__ xin, __nv_bfloat16* __restrict__ sout)
{
    int i = blockIdx.x * 256 + threadIdx.x;
    if (i >= BCN_) return;
    float v = 0.f;
#pragma unroll
    for (int t = 0; t < T_; t++) {
        float xv = xin[(size_t)t * BCN_ + i];
        float h = v + (xv - v) * 0.5f;
        bool sp = (h >= 1.0f);
        sout[(size_t)t * BCN_ + i] = __float2bfloat16(sp ? 1.f : 0.f);
        v = sp ? 0.f : h;
    }
}

// ---------------- cp.async helpers ------------------------------------------------
__device__ __forceinline__ void cpa16(void* s, const void* g)
{
    unsigned int sa = (unsigned int)__cvta_generic_to_shared(s);
    asm volatile("cp.async.cg.shared.global [%0], [%1], 16;\n" :: "r"(sa), "l"(g));
}
__device__ __forceinline__ void cpa_commit() { asm volatile("cp.async.commit_group;\n"); }
template <int NN>
__device__ __forceinline__ void cpa_wait() { asm volatile("cp.async.wait_group %0;\n" :: "n"(NN)); }

// ---------------- fused qkv GEMM + BN + LIF ---------------------------------------
// Tile 64(o) x 256(n), GBK=64, 3-stage, 1 sync per k-iter.
// Bias injected via MMA (acc init = bnb . 1^T, hi/lo exact).
// LIF membrane lives in registers co-indexed with accumulator fragments.
#define FBM 64
#define FBN 256
#define FBK 64
#define FLDA 72                              // 64 + 8
#define FLDB 264                             // 256 + 8
#define FLDC 260                             // fp32 staging row
#define FNT 6
#define FA_ST (FBM * FLDA)                   // 4608 elems
#define FAST (2 * FA_ST)                     // hi + lo: 9216
#define FBST (FBK * FLDB)                    // 16896
#define FSTG (FAST + FBST)                   // 26112 elems = 52224 B
#define FCS_OFF (FSTG * 2)                   // Cs aliases stages 1-2 (52224 B)
#define FBIAS_OFF (3 * FSTG * 2)             // 156672
#define FONES_OFF (FBIAS_OFF + 2 * 64 * 16 * 2)  // 160768
#define FSM (FONES_OFF + 16 * 264 * 2)       // 169216 B

__global__ __launch_bounds__(256, 1)
void gemm_lif_kernel(const __nv_bfloat16* __restrict__ Ahi,
                     const __nv_bfloat16* __restrict__ Alo,
                     const __nv_bfloat16* __restrict__ Bmat,
                     __nv_bfloat16* __restrict__ oq,
                     __nv_bfloat16* __restrict__ ok,
                     __nv_bfloat16* __restrict__ ov)
{
    extern __shared__ char smem[];
    __nv_bfloat16* Sg = (__nv_bfloat16*)smem;
    float*         Cs = (float*)(smem + FCS_OFF);            // 64 x FLDC fp32
    __nv_bfloat16* Bh = (__nv_bfloat16*)(smem + FBIAS_OFF);  // bias hi [64][16]
    __nv_bfloat16* Bl = Bh + 64 * 16;                        // bias lo
    __nv_bfloat16* On = (__nv_bfloat16*)(smem + FONES_OFF);  // ones [16][264]

    int o0 = blockIdx.x * FBM;
    int b  = blockIdx.z;
    int s  = o0 / C_;
    int oc0 = o0 - s * C_;
    __nv_bfloat16* outp = (s == 0) ? oq : (s == 1) ? ok : ov;

    int tid = threadIdx.x;
    int wid = tid >> 5;
    int wm = wid & 1;          // rows wm*32..
    int wn = wid >> 1;         // cols wn*64..

    // build bias tiles (col 0 = bnb hi/lo, rest 0) and ones tile (row 0 = 1)
#pragma unroll
    for (int u = 0; u < 4; u++) {
        int idx = tid + u * 256;
        int r = idx >> 4, c = idx & 15;
        float bv = (c == 0) ? g_bnb[o0 + r] : 0.f;
        __nv_bfloat16 hh = __float2bfloat16(bv);
        Bh[idx] = hh;
        Bl[idx] = __float2bfloat16(bv - __bfloat162float(hh));
    }
    for (int idx = tid; idx < 16 * 264; idx += 256) {
        int r = idx / 264, c = idx - r * 264;
        On[idx] = __float2bfloat16((r == 0 && c < 256) ? 1.f : 0.f);
    }
    __syncthreads();

    float vm[2][4][8];
#pragma unroll
    for (int i = 0; i < 2; i++)
#pragma unroll
        for (int j = 0; j < 4; j++)
#pragma unroll
            for (int e = 0; e < 8; e++) vm[i][j][e] = 0.f;

    auto fill = [&](const __nv_bfloat16* Bp, int kt, int st) {
        __nv_bfloat16* Ah = Sg + st * FSTG;
        __nv_bfloat16* Al = Ah + FA_ST;
        __nv_bfloat16* Bd = Ah + FAST;
        int ka = kt * FBK;
#pragma unroll
        for (int u = 0; u < 2; u++) {             // A hi+lo: 64x64 (512 chunks each)
            int idx = tid + u * 256;
            int r = idx >> 3, c8 = (idx & 7) << 3;
            size_t go = (size_t)(o0 + r) * C_ + ka + c8;
            cpa16(Ah + r * FLDA + c8, Ahi + go);
            cpa16(Al + r * FLDA + c8, Alo + go);
        }
#pragma unroll
        for (int u = 0; u < 8; u++) {             // B: 64x256 (2048 chunks)
            int idx = tid + u * 256;
            int r = idx >> 5, c8 = (idx & 31) << 3;
            cpa16(Bd + r * FLDB + c8, Bp + (size_t)(ka + r) * N_ + c8);
        }
        cpa_commit();
    };

    // prime pipeline for t=0
    {
        const __nv_bfloat16* Bp0 = Bmat + (size_t)(0 * B_ + b) * C_ * N_;
        fill(Bp0, 0, 0);
        fill(Bp0, 1, 1);
    }

#pragma unroll 1
    for (int t = 0; t < T_; t++) {
        const __nv_bfloat16* Bp = Bmat + (size_t)(t * B_ + b) * C_ * N_;

        // acc init = bias via MMA (hi + lo, exact)
        wmma::fragment<wmma::accumulator, 16, 16, 16, float> acc[2][4];
        {
            wmma::fragment<wmma::matrix_b, 16, 16, 16, __nv_bfloat16, wmma::row_major> onef;
            wmma::load_matrix_sync(onef, On, 264);
            wmma::fragment<wmma::matrix_a, 16, 16, 16, __nv_bfloat16, wmma::row_major> bh[2], bl2[2];
#pragma unroll
            for (int i = 0; i < 2; i++) {
                wmma::load_matrix_sync(bh[i],  Bh + (wm * 32 + i * 16) * 16, 16);
                wmma::load_matrix_sync(bl2[i], Bl + (wm * 32 + i * 16) * 16, 16);
            }
#pragma unroll
            for (int i = 0; i < 2; i++)
#pragma unroll
                for (int j = 0; j < 4; j++) {
                    wmma::fill_fragment(acc[i][j], 0.f);
                    wmma::mma_sync(acc[i][j], bh[i],  onef, acc[i][j]);
                    wmma::mma_sync(acc[i][j], bl2[i], onef, acc[i][j]);
                }
        }

        // mainloop: 3-stage, single sync per k-iter
        for (int kt = 0; kt < FNT; kt++) {
            if (kt + 1 < FNT) cpa_wait<1>(); else cpa_wait<0>();
            __syncthreads();
            int st = kt % 3;
            const __nv_bfloat16* Ah = Sg + st * FSTG;
            const __nv_bfloat16* Al = Ah + FA_ST;
            const __nv_bfloat16* Bb = Ah + FAST;
#pragma unroll
            for (int ks = 0; ks < 4; ks++) {
                wmma::fragment<wmma::matrix_b, 16, 16, 16, __nv_bfloat16, wmma::row_major> bfr[4];
#pragma unroll
                for (int j = 0; j < 4; j++)
                    wmma::load_matrix_sync(bfr[j], Bb + (ks * 16) * FLDB + wn * 64 + j * 16, FLDB);
                wmma::fragment<wmma::matrix_a, 16, 16, 16, __nv_bfloat16, wmma::row_major> af[2];
#pragma unroll
                for (int i = 0; i < 2; i++)
                    wmma::load_matrix_sync(af[i], Ah + (wm * 32 + i * 16) * FLDA + ks * 16, FLDA);
#pragma unroll
                for (int i = 0; i < 2; i++)
#pragma unroll
                    for (int j = 0; j < 4; j++)
                        wmma::mma_sync(acc[i][j], af[i], bfr[j], acc[i][j]);
#pragma unroll
                for (int i = 0; i < 2; i++)
                    wmma::load_matrix_sync(af[i], Al + (wm * 32 + i * 16) * FLDA + ks * 16, FLDA);
#pragma unroll
                for (int i = 0; i < 2; i++)
#pragma unroll
                    for (int j = 0; j < 4; j++)
                        wmma::mma_sync(acc[i][j], af[i], bfr[j], acc[i][j]);
            }
            if (kt + 2 < FNT) fill(Bp, kt + 2, (kt + 2) % 3);
        }
        __syncthreads();   // stage reads done (Cs aliases stages 1-2)

        // prefetch t+1 k-tile 0 into stage 0 (not aliased by Cs)
        if (t + 1 < T_) {
            const __nv_bfloat16* Bp1 = Bmat + (size_t)((t + 1) * B_ + b) * C_ * N_;
            fill(Bp1, 0, 0);
        }

        // LIF entirely in registers (mapping-agnostic), spikes into acc
#pragma unroll
        for (int i = 0; i < 2; i++)
#pragma unroll
            for (int j = 0; j < 4; j++)
#pragma unroll
                for (int e = 0; e < 8; e++) {
                    float y = acc[i][j].x[e];
                    float m = vm[i][j][e];
                    float hh = m + (y - m) * 0.5f;
                    bool sp = (hh >= 1.0f);
                    vm[i][j][e] = sp ? 0.f : hh;
                    acc[i][j].x[e] = sp ? 1.f : 0.f;
                }

        // stage spikes (fp32) then convert to bf16 and write
#pragma unroll
        for (int i = 0; i < 2; i++)
#pragma unroll
            for (int j = 0; j < 4; j++)
                wmma::store_matrix_sync(Cs + (wm * 32 + i * 16) * FLDC + wn * 64 + j * 16,
                                        acc[i][j], FLDC, wmma::mem_row_major);
        __syncthreads();

        {
            size_t obase = (size_t)(t * B_ + b) * C_ * N_;
#pragma unroll
            for (int u = 0; u < 16; u++) {       // 64x256 = 4096 float4
                int e = tid + u * 256;
                int r = e >> 6;
                int c4 = (e & 63) << 2;
                float4 val = *(float4*)(Cs + r * FLDC + c4);
                __nv_bfloat162 p0 = __floats2bfloat162_rn(val.x, val.y);
                __nv_bfloat162 p1 = __floats2bfloat162_rn(val.z, val.w);
                uint2 w;
                w.x = *(unsigned int*)&p0;
                w.y = *(unsigned int*)&p1;
                *(uint2*)(outp + obase + (size_t)(oc0 + r) * N_ + c4) = w;
            }
        }
        __syncthreads();

        // now safe to refill stage 1 (was aliased by Cs) for t+1
        if (t + 1 < T_) {
            const __nv_bfloat16* Bp1 = Bmat + (size_t)((t + 1) * B_ + b) * C_ * N_;
            fill(Bp1, 1, 1);
        }
    }
}

// ---------------- proj GEMM + folded BN (identical to R8) -------------------------
#define GBM 128
#define GBN 256
#define GBK 64
#define LDA 72
#define LDB 264
#define LDC 260
#define NT_ 6
#define A_ST (GBM * LDA)
#define AST (2 * A_ST)
#define BST (GBK * LDB)
#define STG_ (AST + BST)
#define GSM (3 * STG_ * 2)                // 211968 B

__global__ __launch_bounds__(256, 1)
void gemm_bn_kernel(const __nv_bfloat16* __restrict__ Ahi,
                    const __nv_bfloat16* __restrict__ Alo,
                    const __nv_bfloat16* __restrict__ Bmat,
                    int ldo, int bnoff, float* __restrict__ out)
{
    extern __shared__ char smem[];
    __nv_bfloat16* Sg = (__nv_bfloat16*)smem;
    float*         Cs = (float*)smem;

    int o0 = blockIdx.x * GBM;
    int tb = blockIdx.z;
    const __nv_bfloat16* Bp = Bmat + (size_t)tb * C_ * N_;
    int tid = threadIdx.x;
    int wid = tid >> 5;
    int wm = wid & 1;
    int wn = wid >> 1;

    wmma::fragment<wmma::accumulator, 16, 16, 16, float> acc[4][4];
#pragma unroll
    for (int i = 0; i < 4; i++)
#pragma unroll
        for (int j = 0; j < 4; j++) wmma::fill_fragment(acc[i][j], 0.f);

    auto fill = [&](int kt, int st) {
        __nv_bfloat16* Ah = Sg + st * STG_;
        __nv_bfloat16* Al = Ah + A_ST;
        __nv_bfloat16* Bd = Ah + AST;
        int ka = kt * GBK;
#pragma unroll
        for (int u = 0; u < 4; u++) {
            int idx = tid + u * 256;
            int r = idx >> 3, c8 = (idx & 7) << 3;
            size_t go = (size_t)(o0 + r) * C_ + ka + c8;
            cpa16(Ah + r * LDA + c8, Ahi + go);
            cpa16(Al + r * LDA + c8, Alo + go);
        }
#pragma unroll
        for (int u = 0; u < 8; u++) {
            int idx = tid + u * 256;
            int r = idx >> 5, c8 = (idx & 31) << 3;
            cpa16(Bd + r * LDB + c8, Bp + (size_t)(ka + r) * N_ + c8);
        }
        cpa_commit();
    };

    fill(0, 0);
    fill(1, 1);
    for (int kt = 0; kt < NT_; kt++) {
        if (kt + 1 < NT_) cpa_wait<1>(); else cpa_wait<0>();
        __syncthreads();
        int st = kt % 3;
        const __nv_bfloat16* Ah = Sg + st * STG_;
        const __nv_bfloat16* Al = Ah + A_ST;
        const __nv_bfloat16* Bb = Ah + AST;
#pragma unroll
        for (int ks = 0; ks < 4; ks++) {
            wmma::fragment<wmma::matrix_b, 16, 16, 16, __nv_bfloat16, wmma::row_major> bfr[4];
#pragma unroll
            for (int j = 0; j < 4; j++)
                wmma::load_matrix_sync(bfr[j], Bb + (ks * 16) * LDB + wn * 64 + j * 16, LDB);
            wmma::fragment<wmma::matrix_a, 16, 16, 16, __nv_bfloat16, wmma::row_major> af[4];
#pragma unroll
            for (int i = 0; i < 4; i++)
                wmma::load_matrix_sync(af[i], Ah + (wm * 64 + i * 16) * LDA + ks * 16, LDA);
#pragma unroll
            for (int i = 0; i < 4; i++)
#pragma unroll
                for (int j = 0; j < 4; j++)
                    wmma::mma_sync(acc[i][j], af[i], bfr[j], acc[i][j]);
#pragma unroll
            for (int i = 0; i < 4; i++)
                wmma::load_matrix_sync(af[i], Al + (wm * 64 + i * 16) * LDA + ks * 16, LDA);
#pragma unroll
            for (int i = 0; i < 4; i++)
#pragma unroll
                for (int j = 0; j < 4; j++)
                    wmma::mma_sync(acc[i][j], af[i], bfr[j], acc[i][j]);
        }
        if (kt + 2 < NT_) fill(kt + 2, (kt + 2) % 3);
    }
    __syncthreads();

#pragma unroll
    for (int i = 0; i < 4; i++)
#pragma unroll
        for (int j = 0; j < 4; j++)
            wmma::store_matrix_sync(Cs + (wm * 64 + i * 16) * LDC + wn * 64 + j * 16,
                                    acc[i][j], LDC, wmma::mem_row_major);
    __syncthreads();

#pragma unroll
    for (int u = 0; u < 32; u++) {
        int e = tid + u * 256;
        int r = e >> 6;
        int c4 = (e & 63) << 2;
        int o = o0 + r;
        float add = g_bnb[bnoff + o];
        float4 val = *(float4*)(Cs + r * LDC + c4);
        val.x += add; val.y += add; val.z += add; val.w += add;
        *(float4*)(out + ((size_t)tb * ldo + o) * N_ + c4) = val;
    }
}

// ---------------- tensor-core attention (identical to R12) ------------------------
#define LDQ 264
#define LDSF 68
#define LDS2 72
#define LDO 68
#define AQ_  0
#define AK_  (64 * LDQ * 2)
#define AV_  (2 * 64 * LDQ * 2)
#define ASF_ (3 * 64 * LDQ * 2)
#define AST2 (ASF_ + 256 * LDSF * 4)
#define ASM_ (AST2 + 256 * LDS2 * 2)           // 207872 B

__global__ __launch_bounds__(256)
void attn_kernel(const __nv_bfloat16* __restrict__ q, const __nv_bfloat16* __restrict__ k,
                 const __nv_bfloat16* __restrict__ v, float* __restrict__ out)
{
    extern __shared__ char smraw[];
    __nv_bfloat16* Qs = (__nv_bfloat16*)(smraw + AQ_);
    __nv_bfloat16* Ks = (__nv_bfloat16*)(smraw + AK_);
    __nv_bfloat16* Vs = (__nv_bfloat16*)(smraw + AV_);
    float*         Sfp = (float*)(smraw + ASF_);
    float*         Osm = (float*)(smraw + ASF_);
    __nv_bfloat16* Stb = (__nv_bfloat16*)(smraw + AST2);

    int blk = blockIdx.x;
    int tb = blk >> 3, h = blk & 7;
    size_t base = ((size_t)tb * C_ + h * D_) * N_;
    int tid = threadIdx.x;
    int wid = tid >> 5;

    const __nv_bfloat16* srcs[3] = { q + base, k + base, v + base };
    __nv_bfloat16* dsts[3] = { Qs, Ks, Vs };
#pragma unroll
    for (int mtx = 0; mtx < 3; mtx++) {
#pragma unroll
        for (int u = 0; u < 6; u++) {
            int idx = tid + u * 256;
            int r = idx >> 5, col = (idx & 31) << 3;
            *(uint4*)(dsts[mtx] + r * LDQ + col) = *(const uint4*)(srcs[mtx] + (size_t)r * N_ + col);
        }
    }
#pragma unroll
    for (int u = 0; u < 2; u++) {
        int idx = tid + u * 256;
        int r = 48 + (idx >> 5), col = (idx & 31) << 3;
        *(uint4*)(Vs + r * LDQ + col) = make_uint4(0, 0, 0, 0);
    }
    __syncthreads();

#pragma unroll 1
    for (int nt = 0; nt < 4; nt++) {
        int n0 = nt * 64;

        {
            int wm2 = wid & 3;
            int wn2 = wid >> 2;
            wmma::fragment<wmma::accumulator, 16, 16, 16, float> sacc[4][2];
#pragma unroll
            for (int i = 0; i < 4; i++)
#pragma unroll
                for (int j = 0; j < 2; j++) wmma::fill_fragment(sacc[i][j], 0.f);
#pragma unroll
            for (int dk = 0; dk < 48; dk += 16) {
                wmma::fragment<wmma::matrix_a, 16, 16, 16, __nv_bfloat16, wmma::col_major> ak[4];
                wmma::fragment<wmma::matrix_b, 16, 16, 16, __nv_bfloat16, wmma::row_major> bq[2];
#pragma unroll
                for (int i = 0; i < 4; i++)
                    wmma::load_matrix_sync(ak[i], Ks + dk * LDQ + wm2 * 64 + i * 16, LDQ);
#pragma unroll
                for (int j = 0; j < 2; j++)
                    wmma::load_matrix_sync(bq[j], Qs + dk * LDQ + n0 + wn2 * 32 + j * 16, LDQ);
#pragma unroll
                for (int i = 0; i < 4; i++)
#pragma unroll
                    for (int j = 0; j < 2; j++)
                        wmma::mma_sync(sacc[i][j], ak[i], bq[j], sacc[i][j]);
            }
#pragma unroll
            for (int i = 0; i < 4; i++)
#pragma unroll
                for (int j = 0; j < 2; j++)
                    wmma::store_matrix_sync(Sfp + (wm2 * 64 + i * 16) * LDSF + wn2 * 32 + j * 16,
                                            sacc[i][j], LDSF, wmma::mem_row_major);
        }
        __syncthreads();

#pragma unroll
        for (int u = 0; u < 16; u++) {
            int idx = tid + u * 256;
            int m = idx >> 4, c4 = (idx & 15) << 2;
            float4 val = *(float4*)(Sfp + m * LDSF + c4);
            __nv_bfloat162 p0 = __floats2bfloat162_rn(val.x, val.y);
            __nv_bfloat162 p1 = __floats2bfloat162_rn(val.z, val.w);
            uint2 w;
            w.x = *(unsigned int*)&p0;
            w.y = *(unsigned int*)&p1;
            *(uint2*)(Stb + m * LDS2 + c4) = w;
        }
        __syncthreads();

        {
            int dr = wid & 1;
            int nc = wid >> 1;
            wmma::fragment<wmma::accumulator, 16, 16, 16, float> oacc[2];
#pragma unroll
            for (int i = 0; i < 2; i++) wmma::fill_fragment(oacc[i], 0.f);
#pragma unroll
            for (int m = 0; m < 256; m += 16) {
                wmma::fragment<wmma::matrix_a, 16, 16, 16, __nv_bfloat16, wmma::row_major> av[2];
                wmma::fragment<wmma::matrix_b, 16, 16, 16, __nv_bfloat16, wmma::row_major> bs;
#pragma unroll
                for (int i = 0; i < 2; i++)
                    wmma::load_matrix_sync(av[i], Vs + (dr * 32 + i * 16) * LDQ + m, LDQ);
                wmma::load_matrix_sync(bs, Stb + m * LDS2 + nc * 16, LDS2);
#pragma unroll
                for (int i = 0; i < 2; i++)
                    wmma::mma_sync(oacc[i], av[i], bs, oacc[i]);
            }
#pragma unroll
            for (int i = 0; i < 2; i++)
                wmma::store_matrix_sync(Osm + (dr * 32 + i * 16) * LDO + nc * 16,
                                        oacc[i], LDO, wmma::mem_row_major);
        }
        __syncthreads();

#pragma unroll
        for (int u = 0; u < 3; u++) {
            int e = tid + u * 256;
            int d = e >> 4, c4 = (e & 15) << 2;
            float4 val = *(float4*)(Osm + d * LDO + c4);
            val.x *= 0.125f; val.y *= 0.125f; val.z *= 0.125f; val.w *= 0.125f;
            *(float4*)(out + base + (size_t)d * N_ + n0 + c4) = val;
        }
        __syncthreads();
    }
}

// ---------------- launch ----------------------------------------------------------
extern "C" void kernel_launch(void* const* d_in, const int* in_sizes, int n_in,
                              void* d_out, int out_size)
{
    const float* x   = (const float*)d_in[0];
    const float* qw  = (const float*)d_in[2];
    const float* qg  = (const float*)d_in[3];
    const float* qb  = (const float*)d_in[4];
    const float* qm  = (const float*)d_in[5];
    const float* qv  = (const float*)d_in[6];
    const float* kw  = (const float*)d_in[7];
    const float* kg  = (const float*)d_in[8];
    const float* kb  = (const float*)d_in[9];
    const float* km  = (const float*)d_in[10];
    const float* kv  = (const float*)d_in[11];
    const float* vw  = (const float*)d_in[12];
    const float* vg  = (const float*)d_in[13];
    const float* vb  = (const float*)d_in[14];
    const float* vm  = (const float*)d_in[15];
    const float* vv  = (const float*)d_in[16];
    const float* pw  = (const float*)d_in[17];
    const float* pbias = (const float*)d_in[18];
    const float* pg  = (const float*)d_in[19];
    const float* pb  = (const float*)d_in[20];
    const float* pm  = (const float*)d_in[21];
    const float* pv  = (const float*)d_in[22];

    void *ps1, *psq, *psk, *psv, *ps2, *pya, *phi, *plo;
    cudaGetSymbolAddress(&ps1, g_s1);
    cudaGetSymbolAddress(&psq, g_sq);
    cudaGetSymbolAddress(&psk, g_sk);
    cudaGetSymbolAddress(&psv, g_sv);
    cudaGetSymbolAddress(&ps2, g_s2);
    cudaGetSymbolAddress(&pya, g_ya);
    cudaGetSymbolAddress(&phi, g_whi);
    cudaGetSymbolAddress(&plo, g_wlo);
    __nv_bfloat16* s1  = (__nv_bfloat16*)ps1;
    __nv_bfloat16* sq  = (__nv_bfloat16*)psq;
    __nv_bfloat16* sk  = (__nv_bfloat16*)psk;
    __nv_bfloat16* sv  = (__nv_bfloat16*)psv;
    __nv_bfloat16* s2  = (__nv_bfloat16*)ps2;
    float*         ya  = (float*)pya;
    __nv_bfloat16* whi = (__nv_bfloat16*)phi;
    __nv_bfloat16* wlo = (__nv_bfloat16*)plo;

    cudaFuncSetAttribute(gemm_lif_kernel, cudaFuncAttributeMaxDynamicSharedMemorySize, FSM);
    cudaFuncSetAttribute(gemm_bn_kernel, cudaFuncAttributeMaxDynamicSharedMemorySize, GSM);
    cudaFuncSetAttribute(attn_kernel, cudaFuncAttributeMaxDynamicSharedMemorySize, ASM_);

    // prep: BN fold first (wconv consumes g_bns)
    bnfold_kernel<<<6, 256>>>(qg, qb, qm, qv, kg, kb, km, kv,
                              vg, vb, vm, vv, pg, pb, pm, pv, pbias);
    wconv_kernel<<<(4 * C_ * C_ + 255) / 256, 256>>>(qw, kw, vw, pw);
    // proj_lif on input
    lif_kernel<<<BCN_ / 256, 256>>>(x, s1);
    // fused q,k,v GEMM + bias-MMA + LIF: (18 o-tiles, 1, 32 b), t-loop inside
    gemm_lif_kernel<<<dim3(M3_ / FBM, 1, B_), 256, FSM>>>(
        whi, wlo, s1, sq, sk, sv);
    // bf16 tensor attention -> fp32
    attn_kernel<<<TBH_, 256, ASM_>>>(sq, sk, sv, ya);
    // attn_lif
    lif_kernel<<<BCN_ / 256, 256>>>(ya, s2);
    // proj GEMM + bias + BN -> final output
    gemm_bn_kernel<<<dim3(C_ / GBM, 1, TB_), 256, GSM>>>(
        whi + 3 * C_ * C_, wlo + 3 * C_ * C_, s2, C_, 3 * C_, (float*)d_out);
}